// round 12
// baseline (speedup 1.0000x reference)
#include <cuda_runtime.h>
#include <math.h>

#define BB 256
#define LL 128
#define DD 300
#define HH 200
#define GG 800
#define DINX 312
#define BL (BB*LL)
#define NEGF (-3.402823466e38f)
#define EPSI 1e-15f
#define FCSPLIT 16
#define LSTM3_SMEM ((200*96 + 200*68 + 64*96)*4)

static __device__ float g_qo[BL*DD];
static __device__ float g_do[BL*DD];
static __device__ float g_tA[BL*DD];
static __device__ float g_qalign[BL*DD];
static __device__ float g_dalign[BL*DD];
static __device__ float g_qself[BL*DD];
static __device__ float g_dself[BL*DD];
static __device__ float g_S[BB*LL*LL];
static __device__ float g_P[BB*LL*LL];
static __device__ float g_rmax[BB*LL];
static __device__ float g_rsum[BB*LL];
static __device__ float g_cmax[BB*LL];
static __device__ float g_csum[BB*LL];
static __device__ float g_scores[4*BB*LL];
static __device__ float g_qmaxp[BB*DD];
static __device__ float g_qmeanp[BB*DD];
static __device__ float g_dmaxp[BB*DD];
static __device__ float g_dmeanp[BB*DD];
static __device__ float g_qcast[BL*DINX];
static __device__ float g_dcast[BL*DINX];
static __device__ float g_Xpre[4][BL*GG];
static __device__ float g_h[2][4*BB*HH];
static __device__ float g_qhid[BL*2*HH];
static __device__ float g_dhid[BL*2*HH];
static __device__ float g_qfin[BB*800];
static __device__ float g_dfin[BB*800];
static __device__ float g_final[BB*3200];
static __device__ float g_fcpart[FCSPLIT][BB*HH];
static __device__ unsigned int g_barG[16*32];

__device__ __forceinline__ float sigf(float x) { return 1.f / (1.f + expf(-x)); }

__device__ __forceinline__ void cpa16(void* dst, const void* src, int bytes) {
    unsigned int d = (unsigned int)__cvta_generic_to_shared(dst);
    asm volatile("cp.async.cg.shared.global [%0], [%1], 16, %2;\n"
                 :: "r"(d), "l"(src), "r"(bytes));
}

// ===== SGEMM v2b: BM=128 BN=64 BK=8, cp.async double-buffer =================
template<int RELU>
__global__ void __launch_bounds__(256) k_sgemm2b(
        const float* __restrict__ A, const float* __restrict__ W,
        const float* __restrict__ bias, float* __restrict__ C,
        int M, int N, int K) {
    __shared__ float As[2][128][12];
    __shared__ float Bs[2][8][64];
    const int tid = threadIdx.x;
    const int m0 = blockIdx.y * 128, n0 = blockIdx.x * 64;
    const int tx = tid & 15, ty = tid >> 4;
    const int am = tid >> 1, ah = (tid & 1) * 4;
    const int bk = tid >> 4, bn = (tid & 15) * 4;
    const float* Ap = A + (size_t)(m0 + am) * K;
    const int NIT = (K + 7) / 8;
    float acc[8][4] = {};

#define SGB_ISSUE(IT, BUF) do {                                               \
    int ka = (IT) * 8 + ah;                                                   \
    int abytes = (K - ka) * 4;                                                \
    abytes = abytes < 0 ? 0 : (abytes > 16 ? 16 : abytes);                    \
    cpa16(&As[BUF][am][ah], Ap + (abytes ? ka : 0), abytes);                  \
    if (tid < 128) {                                                          \
        int kb = (IT) * 8 + bk, n = n0 + bn;                                  \
        int bbytes = 0;                                                       \
        const float* bsrc = W;                                                \
        if (kb < K) {                                                         \
            bbytes = (N - n) * 4;                                             \
            bbytes = bbytes < 0 ? 0 : (bbytes > 16 ? 16 : bbytes);            \
            if (bbytes) bsrc = W + (size_t)kb * N + n;                        \
        }                                                                     \
        cpa16(&Bs[BUF][bk][bn], bsrc, bbytes);                                \
    }                                                                         \
    asm volatile("cp.async.commit_group;\n");                                 \
} while (0)

    SGB_ISSUE(0, 0);
    for (int it = 0; it < NIT; it++) {
        const int cur = it & 1;
        asm volatile("cp.async.wait_group 0;\n");
        __syncthreads();
        if (it + 1 < NIT) SGB_ISSUE(it + 1, cur ^ 1);
#pragma unroll
        for (int kk = 0; kk < 8; kk++) {
            float a[8], b[4];
#pragma unroll
            for (int i = 0; i < 8; i++) a[i] = As[cur][ty * 8 + i][kk];
            *(float4*)b = *(const float4*)&Bs[cur][kk][tx * 4];
#pragma unroll
            for (int i = 0; i < 8; i++)
#pragma unroll
                for (int j = 0; j < 4; j++)
                    acc[i][j] = fmaf(a[i], b[j], acc[i][j]);
        }
    }

    int n = n0 + tx * 4;
    if (n < N) {
        float4 bv = make_float4(0.f, 0.f, 0.f, 0.f);
        if (bias) bv = *(const float4*)(bias + n);
#pragma unroll
        for (int i = 0; i < 8; i++) {
            int m = m0 + ty * 8 + i;
            float4 o;
            o.x = acc[i][0] + bv.x; o.y = acc[i][1] + bv.y;
            o.z = acc[i][2] + bv.z; o.w = acc[i][3] + bv.w;
            if (RELU) {
                o.x = fmaxf(o.x, 0.f); o.y = fmaxf(o.y, 0.f);
                o.z = fmaxf(o.z, 0.f); o.w = fmaxf(o.w, 0.f);
            }
            *(float4*)(C + (size_t)m * N + n) = o;
        }
    }
}

// ===== SGEMM + highway epilogue =============================================
__global__ void __launch_bounds__(256) k_sgemm_hw(
        const float* __restrict__ A, const float* __restrict__ W,
        const float* __restrict__ bias, const float* __restrict__ hrelu,
        const float* __restrict__ x, float* __restrict__ C,
        int M, int N, int K) {
    __shared__ float As[2][128][12];
    __shared__ float Bs[2][8][64];
    const int tid = threadIdx.x;
    const int m0 = blockIdx.y * 128, n0 = blockIdx.x * 64;
    const int tx = tid & 15, ty = tid >> 4;
    const int am = tid >> 1, ah = (tid & 1) * 4;
    const int bk = tid >> 4, bn = (tid & 15) * 4;
    const float* Ap = A + (size_t)(m0 + am) * K;
    const int NIT = (K + 7) / 8;
    float acc[8][4] = {};

    SGB_ISSUE(0, 0);
    for (int it = 0; it < NIT; it++) {
        const int cur = it & 1;
        asm volatile("cp.async.wait_group 0;\n");
        __syncthreads();
        if (it + 1 < NIT) SGB_ISSUE(it + 1, cur ^ 1);
#pragma unroll
        for (int kk = 0; kk < 8; kk++) {
            float a[8], b[4];
#pragma unroll
            for (int i = 0; i < 8; i++) a[i] = As[cur][ty * 8 + i][kk];
            *(float4*)b = *(const float4*)&Bs[cur][kk][tx * 4];
#pragma unroll
            for (int i = 0; i < 8; i++)
#pragma unroll
                for (int j = 0; j < 4; j++)
                    acc[i][j] = fmaf(a[i], b[j], acc[i][j]);
        }
    }
#undef SGB_ISSUE

    int n = n0 + tx * 4;
    if (n < N) {
        float4 bv = *(const float4*)(bias + n);
#pragma unroll
        for (int i = 0; i < 8; i++) {
            int m = m0 + ty * 8 + i;
            float4 hv = *(const float4*)(hrelu + (size_t)m * N + n);
            float4 xv = *(const float4*)(x + (size_t)m * N + n);
            float4 o;
            float t0 = sigf(acc[i][0] + bv.x);
            float t1 = sigf(acc[i][1] + bv.y);
            float t2 = sigf(acc[i][2] + bv.z);
            float t3 = sigf(acc[i][3] + bv.w);
            o.x = t0 * hv.x + (1.f - t0) * xv.x;
            o.y = t1 * hv.y + (1.f - t1) * xv.y;
            o.z = t2 * hv.z + (1.f - t2) * xv.z;
            o.w = t3 * hv.w + (1.f - t3) * xv.w;
            *(float4*)(C + (size_t)m * N + n) = o;
        }
    }
}

// ===== split-K final FC =====================================================
__global__ void __launch_bounds__(256) k_fc_splitk(
        const float* __restrict__ A, const float* __restrict__ W,
        float* __restrict__ part, int M, int N, int K) {
    __shared__ float As[8][132];
    __shared__ float Bs[8][64];
    const int tid = threadIdx.x;
    const int m0 = blockIdx.y * 128, n0 = blockIdx.x * 64;
    const int kz = blockIdx.z;
    const int klo = kz * (K / FCSPLIT), khi = klo + K / FCSPLIT;
    const int tx = tid & 15, ty = tid >> 4;
    const int am = tid >> 1, ac = (tid & 1) * 4;
    const float* Ap = A + (size_t)(m0 + am) * K;
    const int bk = tid >> 4, bn = (tid & 15) * 4;
    float acc[8][4] = {};
    for (int k0 = klo; k0 < khi; k0 += 8) {
        float4 va = *(const float4*)(Ap + k0 + ac);
        float4 vb = make_float4(0.f, 0.f, 0.f, 0.f);
        if (tid < 128) {
            int n = n0 + bn;
            if (n < N) vb = *(const float4*)(W + (size_t)(k0 + bk) * N + n);
        }
        __syncthreads();
        As[ac][am] = va.x; As[ac + 1][am] = va.y;
        As[ac + 2][am] = va.z; As[ac + 3][am] = va.w;
        if (tid < 128) *(float4*)&Bs[bk][bn] = vb;
        __syncthreads();
#pragma unroll
        for (int kk = 0; kk < 8; kk++) {
            float a[8], b[4];
            *(float4*)(a)     = *(const float4*)&As[kk][ty * 8];
            *(float4*)(a + 4) = *(const float4*)&As[kk][ty * 8 + 4];
            *(float4*)(b)     = *(const float4*)&Bs[kk][tx * 4];
#pragma unroll
            for (int i = 0; i < 8; i++)
#pragma unroll
                for (int j = 0; j < 4; j++)
                    acc[i][j] = fmaf(a[i], b[j], acc[i][j]);
        }
    }
    int n = n0 + tx * 4;
    if (n < N) {
#pragma unroll
        for (int i = 0; i < 8; i++) {
            int m = m0 + ty * 8 + i;
            *(float4*)(part + (size_t)kz * M * N + (size_t)m * N + n) = *(float4*)&acc[i][0];
        }
    }
}

__global__ void k_fc_fin(const float* __restrict__ part, const float* __restrict__ bias,
                         float* __restrict__ out) {
    int i = blockIdx.x * blockDim.x + threadIdx.x;
    if (i >= BB * HH) return;
    float s = bias[i % HH];
#pragma unroll
    for (int z = 0; z < FCSPLIT; z++) s += part[(size_t)z * BB * HH + i];
    out[i] = fmaxf(s, 0.f);
}

// ==== batched NT v3 =========================================================
__global__ void __launch_bounds__(256) k_bgemm_nt3(
        const float* __restrict__ A, const float* __restrict__ B,
        float* __restrict__ C, int K) {
    __shared__ float As[2][8][132];
    __shared__ float Bs[2][8][132];
    const int batch = blockIdx.x;
    const float* Ab = A + (size_t)batch * LL * K;
    const float* Bb = B + (size_t)batch * LL * K;
    float* Cb = C + (size_t)batch * LL * LL;
    const int tid = threadIdx.x;
    const int tx = tid & 15, ty = tid >> 4;
    const int am = tid >> 1, ac = (tid & 1) * 4;
    const int NIT = (K + 7) / 8;
    float acc[8][8] = {};
    float4 va, vb;

#define NT_LOAD(IT) do {                                                      \
    int ka = (IT) * 8 + ac;                                                   \
    va = make_float4(0.f, 0.f, 0.f, 0.f);                                     \
    vb = make_float4(0.f, 0.f, 0.f, 0.f);                                     \
    if (ka + 3 < K) {                                                         \
        va = *(const float4*)(Ab + (size_t)am * K + ka);                      \
        vb = *(const float4*)(Bb + (size_t)am * K + ka);                      \
    } else {                                                                  \
        _Pragma("unroll")                                                     \
        for (int j = 0; j < 4; j++)                                           \
            if (ka + j < K) {                                                 \
                ((float*)&va)[j] = Ab[(size_t)am * K + ka + j];               \
                ((float*)&vb)[j] = Bb[(size_t)am * K + ka + j];               \
            }                                                                 \
    }                                                                         \
} while (0)

#define NT_STS(BUF) do {                                                      \
    _Pragma("unroll")                                                         \
    for (int j = 0; j < 4; j++) {                                             \
        As[BUF][ac + j][am] = ((float*)&va)[j];                               \
        Bs[BUF][ac + j][am] = ((float*)&vb)[j];                               \
    }                                                                         \
} while (0)

    NT_LOAD(0);
    NT_STS(0);
    __syncthreads();
    for (int it = 0; it < NIT; it++) {
        const int cur = it & 1;
        if (it + 1 < NIT) NT_LOAD(it + 1);
#pragma unroll
        for (int kk = 0; kk < 8; kk++) {
            float a[8], b[8];
            *(float4*)(a)     = *(const float4*)&As[cur][kk][ty * 8];
            *(float4*)(a + 4) = *(const float4*)&As[cur][kk][ty * 8 + 4];
            *(float4*)(b)     = *(const float4*)&Bs[cur][kk][tx * 8];
            *(float4*)(b + 4) = *(const float4*)&Bs[cur][kk][tx * 8 + 4];
#pragma unroll
            for (int i = 0; i < 8; i++)
#pragma unroll
                for (int j = 0; j < 8; j++)
                    acc[i][j] = fmaf(a[i], b[j], acc[i][j]);
        }
        if (it + 1 < NIT) {
            NT_STS(cur ^ 1);
            __syncthreads();
        }
    }
#undef NT_LOAD
#undef NT_STS
#pragma unroll
    for (int i = 0; i < 8; i++) {
        float* crow = Cb + (size_t)(ty * 8 + i) * LL + tx * 8;
        *(float4*)(crow)     = *(float4*)&acc[i][0];
        *(float4*)(crow + 4) = *(float4*)&acc[i][4];
    }
}

// ==== batched NN v3 =========================================================
__global__ void __launch_bounds__(256) k_bgemm_nn3(
        const float* __restrict__ P, const float* __restrict__ X,
        float* __restrict__ C, int N) {
    __shared__ float As[2][8][132];
    __shared__ float Bs[2][8][64];
    const int batch = blockIdx.y;
    const int n0 = blockIdx.x * 64;
    const float* Ab = P + (size_t)batch * LL * LL;
    const float* Xb = X + (size_t)batch * LL * N;
    float* Cb = C + (size_t)batch * LL * N;
    const int tid = threadIdx.x;
    const int tx = tid & 15, ty = tid >> 4;
    const int am = tid >> 1, ac = (tid & 1) * 4;
    const int bk = tid >> 4, bn = (tid & 15) * 4;
    float acc[8][4] = {};
    float4 va, vb;

#define NN_LOAD(IT) do {                                                      \
    va = *(const float4*)(Ab + (size_t)am * LL + (IT) * 8 + ac);              \
    vb = make_float4(0.f, 0.f, 0.f, 0.f);                                     \
    if (tid < 128) {                                                          \
        int n = n0 + bn;                                                      \
        if (n < N) vb = *(const float4*)(Xb + (size_t)((IT) * 8 + bk) * N + n); \
    }                                                                         \
} while (0)

#define NN_STS(BUF) do {                                                      \
    As[BUF][ac][am] = va.x; As[BUF][ac + 1][am] = va.y;                       \
    As[BUF][ac + 2][am] = va.z; As[BUF][ac + 3][am] = va.w;                   \
    if (tid < 128) *(float4*)&Bs[BUF][bk][bn] = vb;                           \
} while (0)

    NN_LOAD(0);
    NN_STS(0);
    __syncthreads();
    for (int it = 0; it < LL / 8; it++) {
        const int cur = it & 1;
        if (it + 1 < LL / 8) NN_LOAD(it + 1);
#pragma unroll
        for (int kk = 0; kk < 8; kk++) {
            float a[8], b[4];
            *(float4*)(a)     = *(const float4*)&As[cur][kk][ty * 8];
            *(float4*)(a + 4) = *(const float4*)&As[cur][kk][ty * 8 + 4];
            *(float4*)(b)     = *(const float4*)&Bs[cur][kk][tx * 4];
#pragma unroll
            for (int i = 0; i < 8; i++)
#pragma unroll
                for (int j = 0; j < 4; j++)
                    acc[i][j] = fmaf(a[i], b[j], acc[i][j]);
        }
        if (it + 1 < LL / 8) {
            NN_STS(cur ^ 1);
            __syncthreads();
        }
    }
#undef NN_LOAD
#undef NN_STS
    int n = n0 + tx * 4;
    if (n < N) {
#pragma unroll
        for (int i = 0; i < 8; i++)
            *(float4*)(Cb + (size_t)(ty * 8 + i) * N + n) = *(float4*)&acc[i][0];
    }
}

// ==== batched TN v3 =========================================================
__global__ void __launch_bounds__(256) k_bgemm_tn3(
        const float* __restrict__ P, const float* __restrict__ X,
        float* __restrict__ C, int N) {
    __shared__ float As[2][8][132];
    __shared__ float Bs[2][8][64];
    const int batch = blockIdx.y;
    const int n0 = blockIdx.x * 64;
    const float* Ab = P + (size_t)batch * LL * LL;
    const float* Xb = X + (size_t)batch * LL * N;
    float* Cb = C + (size_t)batch * LL * N;
    const int tid = threadIdx.x;
    const int tx = tid & 15, ty = tid >> 4;
    const int lk = tid >> 5, mc = (tid & 31) * 4;
    const int bk = tid >> 4, bn = (tid & 15) * 4;
    float acc[8][4] = {};
    float4 va, vb;

#define TN_LOAD(IT) do {                                                      \
    va = *(const float4*)(Ab + (size_t)((IT) * 8 + lk) * LL + mc);            \
    vb = make_float4(0.f, 0.f, 0.f, 0.f);                                     \
    if (tid < 128) {                                                          \
        int n = n0 + bn;                                                      \
        if (n < N) vb = *(const float4*)(Xb + (size_t)((IT) * 8 + bk) * N + n); \
    }                                                                         \
} while (0)

#define TN_STS(BUF) do {                                                      \
    *(float4*)&As[BUF][lk][mc] = va;                                          \
    if (tid < 128) *(float4*)&Bs[BUF][bk][bn] = vb;                           \
} while (0)

    TN_LOAD(0);
    TN_STS(0);
    __syncthreads();
    for (int it = 0; it < LL / 8; it++) {
        const int cur = it & 1;
        if (it + 1 < LL / 8) TN_LOAD(it + 1);
#pragma unroll
        for (int kk = 0; kk < 8; kk++) {
            float a[8], b[4];
            *(float4*)(a)     = *(const float4*)&As[cur][kk][ty * 8];
            *(float4*)(a + 4) = *(const float4*)&As[cur][kk][ty * 8 + 4];
            *(float4*)(b)     = *(const float4*)&Bs[cur][kk][tx * 4];
#pragma unroll
            for (int i = 0; i < 8; i++)
#pragma unroll
                for (int j = 0; j < 4; j++)
                    acc[i][j] = fmaf(a[i], b[j], acc[i][j]);
        }
        if (it + 1 < LL / 8) {
            TN_STS(cur ^ 1);
            __syncthreads();
        }
    }
#undef TN_LOAD
#undef TN_STS
    int n = n0 + tx * 4;
    if (n < N) {
#pragma unroll
        for (int i = 0; i < 8; i++)
            *(float4*)(Cb + (size_t)(ty * 8 + i) * N + n) = *(float4*)&acc[i][0];
    }
}

__global__ void k_rowred(const float* __restrict__ S, const int* __restrict__ ql,
                         const int* __restrict__ dl, float* __restrict__ rmax,
                         float* __restrict__ rsum) {
    int row = blockIdx.x * 4 + (threadIdx.x >> 5);
    int b = row / LL, q = row % LL;
    int lane = threadIdx.x & 31;
    int QL = ql[b], DL = dl[b];
    bool qv = q < QL;
    float m = NEGF, s = 0.f;
    for (int k = lane; k < LL; k += 32) {
        float v = S[(size_t)row * LL + k];
        bool valid = qv && (k < DL);
        m = fmaxf(m, valid ? v : NEGF);
        s += valid ? v : 0.f;
    }
    for (int o = 16; o; o >>= 1) {
        m = fmaxf(m, __shfl_xor_sync(0xffffffffu, m, o));
        s += __shfl_xor_sync(0xffffffffu, s, o);
    }
    if (lane == 0) { rmax[row] = m; rsum[row] = s; }
}

__global__ void k_colred(const float* __restrict__ S, const int* __restrict__ ql,
                         const int* __restrict__ dl, float* __restrict__ cmax,
                         float* __restrict__ csum) {
    int b = blockIdx.y;
    int k = blockIdx.x * 32 + threadIdx.x;
    int QL = ql[b], DL = dl[b];
    bool kv = k < DL;
    float m = NEGF, s = 0.f;
    for (int q = threadIdx.y; q < LL; q += 8) {
        float v = S[((size_t)b * LL + q) * LL + k];
        bool valid = kv && (q < QL);
        m = fmaxf(m, valid ? v : NEGF);
        s += valid ? v : 0.f;
    }
    __shared__ float sm[8][33];
    __shared__ float ss[8][33];
    sm[threadIdx.y][threadIdx.x] = m;
    ss[threadIdx.y][threadIdx.x] = s;
    __syncthreads();
    if (threadIdx.y == 0) {
        for (int r = 1; r < 8; r++) {
            m = fmaxf(m, sm[r][threadIdx.x]);
            s += ss[r][threadIdx.x];
        }
        cmax[b * LL + k] = m;
        csum[b * LL + k] = s;
    }
}

__global__ void k_softmax1d(const int* __restrict__ ql, const int* __restrict__ dl) {
    int type = blockIdx.x, b = blockIdx.y, i = threadIdx.x;
    float v;
    if (type == 0) v = g_rmax[b * LL + i];
    else if (type == 1) v = g_rsum[b * LL + i] / ((float)dl[b] + EPSI);
    else if (type == 2) v = g_cmax[b * LL + i];
    else v = g_csum[b * LL + i] / ((float)ql[b] + EPSI);
    __shared__ float red[4];
    float m = v;
    for (int o = 16; o; o >>= 1) m = fmaxf(m, __shfl_xor_sync(0xffffffffu, m, o));
    if ((i & 31) == 0) red[i >> 5] = m;
    __syncthreads();
    m = fmaxf(fmaxf(red[0], red[1]), fmaxf(red[2], red[3]));
    __syncthreads();
    float e = expf(v - m);
    float s = e;
    for (int o = 16; o; o >>= 1) s += __shfl_xor_sync(0xffffffffu, s, o);
    if ((i & 31) == 0) red[i >> 5] = s;
    __syncthreads();
    s = red[0] + red[1] + red[2] + red[3];
    g_scores[type * BB * LL + b * LL + i] = e / s;
}

__global__ void k_pool_scored(const float* __restrict__ qo, const float* __restrict__ dob) {
    int b = blockIdx.x;
    int d = threadIdx.x;
    if (d >= DD) return;
    const float* s0 = g_scores + 0 * BB * LL + b * LL;
    const float* s1 = g_scores + 1 * BB * LL + b * LL;
    const float* s2 = g_scores + 2 * BB * LL + b * LL;
    const float* s3 = g_scores + 3 * BB * LL + b * LL;
    float a0 = 0, a1 = 0, a2 = 0, a3 = 0;
    for (int t = 0; t < LL; t++) {
        float qv = qo[((size_t)b * LL + t) * DD + d];
        float dv = dob[((size_t)b * LL + t) * DD + d];
        a0 += s0[t] * qv; a1 += s1[t] * qv;
        a2 += s2[t] * dv; a3 += s3[t] * dv;
    }
    g_qmaxp[b * DD + d] = a0;
    g_qmeanp[b * DD + d] = a1;
    g_dmaxp[b * DD + d] = a2;
    g_dmeanp[b * DD + d] = a3;
}

__global__ void k_rowsoftmax(const float* __restrict__ S, float* __restrict__ P,
                             const int* __restrict__ ql, const int* __restrict__ dl,
                             int mode) {
    int q = blockIdx.x, b = blockIdx.y, k = threadIdx.x;
    bool valid;
    if (mode == 0) valid = (q < ql[b]) && (k < dl[b]);
    else if (mode == 1) valid = (k < ql[b]);
    else valid = (k < dl[b]);
    size_t idx = ((size_t)b * LL + q) * LL + k;
    float v = valid ? S[idx] : NEGF;
    __shared__ float red[4];
    float m = v;
    for (int o = 16; o; o >>= 1) m = fmaxf(m, __shfl_xor_sync(0xffffffffu, m, o));
    if ((k & 31) == 0) red[k >> 5] = m;
    __syncthreads();
    m = fmaxf(fmaxf(red[0], red[1]), fmaxf(red[2], red[3]));
    __syncthreads();
    float e = expf(v - m);
    float s = e;
    for (int o = 16; o; o >>= 1) s += __shfl_xor_sync(0xffffffffu, s, o);
    if ((k & 31) == 0) red[k >> 5] = s;
    __syncthreads();
    s = red[0] + red[1] + red[2] + red[3];
    P[idx] = e / s;
}

__global__ void k_colsoftmax(const float* __restrict__ S, float* __restrict__ P,
                             const int* __restrict__ ql, const int* __restrict__ dl) {
    int b = blockIdx.y;
    int k = blockIdx.x * 32 + threadIdx.x;
    int QL = ql[b], DL = dl[b];
    bool kv = k < DL;
    float v[16];
    float m = NEGF;
#pragma unroll
    for (int j = 0; j < 16; j++) {
        int q = threadIdx.y + 8 * j;
        bool valid = kv && (q < QL);
        v[j] = valid ? S[((size_t)b * LL + q) * LL + k] : NEGF;
        m = fmaxf(m, v[j]);
    }
    __shared__ float sm[8][33];
    sm[threadIdx.y][threadIdx.x] = m;
    __syncthreads();
    m = sm[0][threadIdx.x];
    for (int r = 1; r < 8; r++) m = fmaxf(m, sm[r][threadIdx.x]);
    __syncthreads();
    float e[16];
    float s = 0.f;
#pragma unroll
    for (int j = 0; j < 16; j++) { e[j] = expf(v[j] - m); s += e[j]; }
    sm[threadIdx.y][threadIdx.x] = s;
    __syncthreads();
    s = 0.f;
    for (int r = 0; r < 8; r++) s += sm[r][threadIdx.x];
#pragma unroll
    for (int j = 0; j < 16; j++) {
        int q = threadIdx.y + 8 * j;
        P[((size_t)b * LL + q) * LL + k] = e[j] / s;
    }
}

__global__ void k_cast(const float* __restrict__ emb, const float* __restrict__ xo,
                       const float* __restrict__ maxp, const float* __restrict__ meanp,
                       const float* __restrict__ align, const float* __restrict__ selfa,
                       const float* __restrict__ Wc, const float* __restrict__ bc,
                       const float* __restrict__ Wm, const float* __restrict__ bm,
                       const float* __restrict__ Ws, const float* __restrict__ bs,
                       int ibase, float* __restrict__ cast) {
    int bt = blockIdx.x;
    int b = bt / LL;
    int tid = threadIdx.x;
    float sc[4] = {0, 0, 0, 0}, smv[4] = {0, 0, 0, 0}, ssv[4] = {0, 0, 0, 0};
    for (int d = tid; d < DD; d += 128) {
        float e = emb[(size_t)bt * DD + d];
        float x[4];
        x[0] = maxp[b * DD + d];
        x[1] = meanp[b * DD + d];
        x[2] = align[(size_t)bt * DD + d];
        x[3] = selfa[(size_t)bt * DD + d];
#pragma unroll
        for (int i = 0; i < 4; i++) {
            const float* wc = Wc + (ibase + i) * 600;
            sc[i] += x[i] * wc[d] + e * wc[300 + d];
            smv[i] += x[i] * e * Wm[(ibase + i) * 300 + d];
            ssv[i] += (x[i] - e) * Ws[(ibase + i) * 300 + d];
        }
    }
    __shared__ float red[12][4];
    int lane = tid & 31, w = tid >> 5;
#pragma unroll
    for (int i = 0; i < 4; i++) {
        for (int o = 16; o; o >>= 1) {
            sc[i] += __shfl_xor_sync(0xffffffffu, sc[i], o);
            smv[i] += __shfl_xor_sync(0xffffffffu, smv[i], o);
            ssv[i] += __shfl_xor_sync(0xffffffffu, ssv[i], o);
        }
        if (lane == 0) {
            red[i * 3 + 0][w] = sc[i];
            red[i * 3 + 1][w] = smv[i];
            red[i * 3 + 2][w] = ssv[i];
        }
    }
    __syncthreads();
    if (tid < 12) {
        float v = red[tid][0] + red[tid][1] + red[tid][2] + red[tid][3];
        int i = tid / 3, kind = tid % 3;
        float bv = (kind == 0) ? bc[ibase + i] : (kind == 1) ? bm[ibase + i] : bs[ibase + i];
        cast[(size_t)bt * DINX + tid] = fmaxf(v + bv, 0.f);
    }
    for (int j = tid; j < DD; j += 128)
        cast[(size_t)bt * DINX + 12 + j] = xo[(size_t)bt * DD + j];
}

__global__ void k_init() {
    int i = blockIdx.x * blockDim.x + threadIdx.x;
    if (i < 16 * 32) g_barG[i] = 0u;
    if (i < 4 * BB * HH) g_h[0][i] = 0.f;
}

// ======== persistent 4-way LSTM v4: 144 blocks, z staged through SMEM =======
// grid = 4 dirs x 4 batch-tiles(64) x 9 unit-tiles(24)
__global__ void __launch_bounds__(256, 1) k_lstm3(
        const float* __restrict__ qWh, const float* __restrict__ dWh,
        const float* __restrict__ qb, const float* __restrict__ db) {
    extern __shared__ float smx[];
    float* Ws = smx;                       // [200][96] col = uu*4+gate
    float* hs = smx + 200 * 96;            // [200][68] transposed h_prev
    float* zb = smx + 200 * 96 + 200 * 68; // [64][96]  raw z

    const int bx = blockIdx.x;
    const int l = bx / 36, rem = bx % 36;
    const int bt = rem / 9, ut = rem % 9;
    const int b0 = bt * 64, u0 = ut * 24;
    const int grp = l * 4 + bt;
    const int tid = threadIdx.x;
    const int tx = tid & 31, ty = tid >> 5;
    const float* Wh = ((l < 2) ? qWh : dWh) + (size_t)(l & 1) * HH * GG;
    const float* bias = ((l < 2) ? qb : db) + (size_t)(l & 1) * GG;
    float* hid = (l < 2) ? g_qhid : g_dhid;
    const int hoff = (l & 1) * HH;
    const float* Xp = g_Xpre[l];

    for (int idx = tid; idx < 200 * 96; idx += 256) {
        int k = idx / 96, c = idx % 96;
        int uu = c >> 2, gate = c & 3;
        int u = u0 + uu;
        Ws[idx] = (u < HH) ? Wh[(size_t)k * GG + gate * HH + u] : 0.f;
    }
    // fixed epilogue cell mapping: 6 cells per thread, cell = tid + 256*p
    int crow[6], cu[6];
    bool cval[6];
    float breg[6][4], creg[6];
#pragma unroll
    for (int p = 0; p < 6; p++) {
        int cell = tid + 256 * p;
        crow[p] = cell / 24;
        int uu = cell % 24;
        cu[p] = u0 + uu;
        cval[p] = (cu[p] < HH);
#pragma unroll
        for (int g = 0; g < 4; g++)
            breg[p][g] = cval[p] ? bias[g * HH + cu[p]] : 0.f;
        creg[p] = 0.f;
    }
    __syncthreads();

    for (int t = 0; t < LL; t++) {
        const int pos = (l & 1) ? (LL - 1 - t) : t;
        const float* hprev = g_h[t & 1] + l * BB * HH;

        for (int idx = tid; idx < 64 * 50; idx += 256) {
            int bl = idx / 50, c4 = (idx % 50) * 4;
            float4 v = *(const float4*)(hprev + (size_t)(b0 + bl) * HH + c4);
            hs[(c4 + 0) * 68 + bl] = v.x;
            hs[(c4 + 1) * 68 + bl] = v.y;
            hs[(c4 + 2) * 68 + bl] = v.z;
            hs[(c4 + 3) * 68 + bl] = v.w;
        }
        __syncthreads();

        float acc[8][3] = {};
        {
            const float* hp = hs + ty * 8;
            const float* wp = Ws + tx * 3;
#pragma unroll 2
            for (int k = 0; k < HH; k++) {
                float a[8], b[3];
                *(float4*)(a)     = *(const float4*)(hp + k * 68);
                *(float4*)(a + 4) = *(const float4*)(hp + k * 68 + 4);
                b[0] = wp[k * 96]; b[1] = wp[k * 96 + 1]; b[2] = wp[k * 96 + 2];
#pragma unroll
                for (int i = 0; i < 8; i++)
#pragma unroll
                    for (int j = 0; j < 3; j++)
                        acc[i][j] = fmaf(a[i], b[j], acc[i][j]);
            }
        }
#pragma unroll
        for (int i = 0; i < 8; i++) {
            float* zr = zb + (ty * 8 + i) * 96 + tx * 3;
            zr[0] = acc[i][0]; zr[1] = acc[i][1]; zr[2] = acc[i][2];
        }
        __syncthreads();

        float* hnext = g_h[(t + 1) & 1] + l * BB * HH;
#pragma unroll
        for (int p = 0; p < 6; p++) {
            if (!cval[p]) continue;
            int row = crow[p], u = cu[p];
            int bb = b0 + row;
            const float* zr = zb + row * 96 + (u - u0) * 4;
            const float* xr = Xp + ((size_t)bb * LL + pos) * GG;
            float zi = zr[0] + xr[0 * HH + u] + breg[p][0];
            float zf = zr[1] + xr[1 * HH + u] + breg[p][1];
            float zg = zr[2] + xr[2 * HH + u] + breg[p][2];
            float zo = zr[3] + xr[3 * HH + u] + breg[p][3];
            float cn = sigf(zf) * creg[p] + sigf(zi) * tanhf(zg);
            float hn = sigf(zo) * tanhf(cn);
            creg[p] = cn;
            hnext[(size_t)bb * HH + u] = hn;
            hid[((size_t)bb * LL + pos) * (2 * HH) + hoff + u] = hn;
        }

        __syncthreads();
        if (tid == 0) {
            __threadfence();
            atomicAdd(&g_barG[grp * 32], 1u);
            unsigned tgt = 9u * (unsigned)(t + 1);
            while (*((volatile unsigned int*)&g_barG[grp * 32]) < tgt) {}
            __threadfence();
        }
        __syncthreads();
    }
}

__global__ void k_pool(const float* __restrict__ hid, const int* __restrict__ len,
                       float* __restrict__ fin) {
    int b = blockIdx.x, tid = threadIdx.x;
    if (tid >= 400) return;
    int Lv = len[b];
    float s = 0.f, m = NEGF;
    for (int t = 0; t < LL; t++) {
        float v = (t < Lv) ? hid[((size_t)b * LL + t) * 400 + tid] : 0.f;
        s += v;
        m = fmaxf(m, v);
    }
    fin[b * 800 + tid] = s / ((float)Lv + EPSI);
    fin[b * 800 + 400 + tid] = m;
}

__global__ void k_buildfinal() {
    int i = blockIdx.x * blockDim.x + threadIdx.x;
    if (i >= BB * 3200) return;
    int b = i / 3200, j = i % 3200;
    float v;
    if (j < 800) v = g_qfin[b * 800 + j];
    else if (j < 1600) v = g_dfin[b * 800 + j - 800];
    else if (j < 2400) v = g_qfin[b * 800 + j - 1600] * g_dfin[b * 800 + j - 1600];
    else v = g_qfin[b * 800 + j - 2400] - g_dfin[b * 800 + j - 2400];
    g_final[i] = v;
}

static float* symaddr(const void* sym) {
    void* p = nullptr;
    cudaGetSymbolAddress(&p, sym);
    return (float*)p;
}

extern "C" void kernel_launch(void* const* d_in, const int* in_sizes, int n_in,
                              void* d_out, int out_size) {
    (void)in_sizes; (void)n_in; (void)out_size;
    const float* query_emb = (const float*)d_in[0];
    const float* doc_emb   = (const float*)d_in[1];
    const int*   query_len = (const int*)d_in[2];
    const int*   doc_len   = (const int*)d_in[3];
    const float* Mw        = (const float*)d_in[4];
    const float* hwq_Wt    = (const float*)d_in[5];
    const float* hwq_bt    = (const float*)d_in[6];
    const float* hwq_Wh    = (const float*)d_in[7];
    const float* hwq_bh    = (const float*)d_in[8];
    const float* hwd_Wt    = (const float*)d_in[9];
    const float* hwd_bt    = (const float*)d_in[10];
    const float* hwd_Wh    = (const float*)d_in[11];
    const float* hwd_bh    = (const float*)d_in[12];
    const float* cWc       = (const float*)d_in[13];
    const float* cbc       = (const float*)d_in[14];
    const float* cWm       = (const float*)d_in[15];
    const float* cbm       = (const float*)d_in[16];
    const float* cWs       = (const float*)d_in[17];
    const float* cbs       = (const float*)d_in[18];
    const float* qWx       = (const float*)d_in[19];
    const float* qWh       = (const float*)d_in[20];
    const float* qb        = (const float*)d_in[21];
    const float* dWx       = (const float*)d_in[22];
    const float* dWh       = (const float*)d_in[23];
    const float* db        = (const float*)d_in[24];
    const float* fc1_W     = (const float*)d_in[25];
    const float* fc1_b     = (const float*)d_in[26];

    float* qo     = symaddr(g_qo);
    float* dob    = symaddr(g_do);
    float* tA     = symaddr(g_tA);
    float* qalign = symaddr(g_qalign);
    float* dalign = symaddr(g_dalign);
    float* qself  = symaddr(g_qself);
    float* dself  = symaddr(g_dself);
    float* S      = symaddr(g_S);
    float* P      = symaddr(g_P);
    float* qcast  = symaddr(g_qcast);
    float* dcast  = symaddr(g_dcast);
    float* Xpre   = symaddr(g_Xpre);
    float* qhid   = symaddr(g_qhid);
    float* dhid   = symaddr(g_dhid);
    float* qfin   = symaddr(g_qfin);
    float* dfin   = symaddr(g_dfin);
    float* finalb = symaddr(g_final);
    float* fcpart = symaddr(g_fcpart);
    float* qmaxp  = symaddr(g_qmaxp);
    float* qmeanp = symaddr(g_qmeanp);
    float* dmaxp  = symaddr(g_dmaxp);
    float* dmeanp = symaddr(g_dmeanp);

    static int smem_set = 0;
    if (!smem_set) {
        cudaFuncSetAttribute(k_lstm3, cudaFuncAttributeMaxDynamicSharedMemorySize, LSTM3_SMEM);
        smem_set = 1;
    }

    const int EW = 256;
    dim3 gD(5, 256);
    dim3 gG(13, 256);
    dim3 gB(5, BB);

    k_sgemm2b<1><<<gD, 256>>>(query_emb, hwq_Wh, hwq_bh, tA, BL, DD, DD);
    k_sgemm_hw<<<gD, 256>>>(query_emb, hwq_Wt, hwq_bt, tA, query_emb, qo, BL, DD, DD);
    k_sgemm2b<1><<<gD, 256>>>(doc_emb, hwd_Wh, hwd_bh, tA, BL, DD, DD);
    k_sgemm_hw<<<gD, 256>>>(doc_emb, hwd_Wt, hwd_bt, tA, doc_emb, dob, BL, DD, DD);

    k_sgemm2b<0><<<gD, 256>>>(qo, Mw, nullptr, tA, BL, DD, DD);
    k_bgemm_nt3<<<BB, 256>>>(tA, dob, S, DD);

    k_rowred<<<BB * LL / 4, 128>>>(S, query_len, doc_len, symaddr(g_rmax), symaddr(g_rsum));
    k_colred<<<dim3(4, BB), dim3(32, 8)>>>(S, query_len, doc_len, symaddr(g_cmax), symaddr(g_csum));
    k_softmax1d<<<dim3(4, BB), 128>>>(query_len, doc_len);
    k_pool_scored<<<BB, 320>>>(qo, dob);

    k_rowsoftmax<<<dim3(LL, BB), 128>>>(S, P, query_len, doc_len, 0);
    k_bgemm_nn3<<<gB, 256>>>(P, dob, qalign, DD);
    k_colsoftmax<<<dim3(4, BB), dim3(32, 8)>>>(S, P, query_len, doc_len);
    k_bgemm_tn3<<<gB, 256>>>(P, qo, dalign, DD);

    k_bgemm_nt3<<<BB, 256>>>(qo, qo, S, DD);
    k_rowsoftmax<<<dim3(LL, BB), 128>>>(S, P, query_len, doc_len, 1);
    k_bgemm_nn3<<<gB, 256>>>(P, qo, qself, DD);
    k_bgemm_nt3<<<BB, 256>>>(dob, dob, S, DD);
    k_rowsoftmax<<<dim3(LL, BB), 128>>>(S, P, query_len, doc_len, 2);
    k_bgemm_nn3<<<gB, 256>>>(P, dob, dself, DD);

    k_cast<<<BL, 128>>>(query_emb, qo, qmaxp, qmeanp, qalign, qself,
                        cWc, cbc, cWm, cbm, cWs, cbs, 0, qcast);
    k_cast<<<BL, 128>>>(doc_emb, dob, dmaxp, dmeanp, dalign, dself,
                        cWc, cbc, cWm, cbm, cWs, cbs, 4, dcast);

    k_sgemm2b<0><<<gG, 256>>>(qcast, qWx,             nullptr, Xpre + (size_t)0 * BL * GG, BL, GG, DINX);
    k_sgemm2b<0><<<gG, 256>>>(qcast, qWx + DINX * GG, nullptr, Xpre + (size_t)1 * BL * GG, BL, GG, DINX);
    k_sgemm2b<0><<<gG, 256>>>(dcast, dWx,             nullptr, Xpre + (size_t)2 * BL * GG, BL, GG, DINX);
    k_sgemm2b<0><<<gG, 256>>>(dcast, dWx + DINX * GG, nullptr, Xpre + (size_t)3 * BL * GG, BL, GG, DINX);

    k_init<<<(4 * BB * HH + EW - 1) / EW, EW>>>();
    k_lstm3<<<144, 256, LSTM3_SMEM>>>(qWh, dWh, qb, db);

    k_pool<<<BB, 512>>>(qhid, query_len, qfin);
    k_pool<<<BB, 512>>>(dhid, doc_len, dfin);
    k_buildfinal<<<(BB * 3200 + EW - 1) / EW, EW>>>();

    k_fc_splitk<<<dim3(4, 2, FCSPLIT), 256>>>(finalb, fc1_W, fcpart, BB, HH, 3200);
    k_fc_fin<<<(BB * HH + EW - 1) / EW, EW>>>(fcpart, fc1_b, (float*)d_out);
}

// round 13
// speedup vs baseline: 1.0395x; 1.0395x over previous
#include <cuda_runtime.h>
#include <math.h>

#define BB 256
#define LL 128
#define DD 300
#define HH 200
#define GG 800
#define DINX 312
#define BL (BB*LL)
#define NEGF (-3.402823466e38f)
#define EPSI 1e-15f
#define FCSPLIT 16
#define LSTM_SMEM 156800

static __device__ float g_qo[BL*DD];
static __device__ float g_do[BL*DD];
static __device__ float g_tA[BL*DD];
static __device__ float g_qalign[BL*DD];
static __device__ float g_dalign[BL*DD];
static __device__ float g_qself[BL*DD];
static __device__ float g_dself[BL*DD];
static __device__ float g_S[BB*LL*LL];
static __device__ float g_P[BB*LL*LL];
static __device__ float g_rmax[BB*LL];
static __device__ float g_rsum[BB*LL];
static __device__ float g_cmax[BB*LL];
static __device__ float g_csum[BB*LL];
static __device__ float g_scores[4*BB*LL];
static __device__ float g_qmaxp[BB*DD];
static __device__ float g_qmeanp[BB*DD];
static __device__ float g_dmaxp[BB*DD];
static __device__ float g_dmeanp[BB*DD];
static __device__ float g_qcast[BL*DINX];
static __device__ float g_dcast[BL*DINX];
static __device__ float g_Xpre[4][BL*GG];
static __device__ float g_h[2][4*BB*HH];
static __device__ float g_qhid[BL*2*HH];
static __device__ float g_dhid[BL*2*HH];
static __device__ float g_qfin[BB*800];
static __device__ float g_dfin[BB*800];
static __device__ float g_fcpart[FCSPLIT][BB*HH];
static __device__ unsigned int g_barG[16*32];

__device__ __forceinline__ float sigf(float x) { return 1.f / (1.f + expf(-x)); }

__device__ __forceinline__ void cpa16(void* dst, const void* src, int bytes) {
    unsigned int d = (unsigned int)__cvta_generic_to_shared(dst);
    asm volatile("cp.async.cg.shared.global [%0], [%1], 16, %2;\n"
                 :: "r"(d), "l"(src), "r"(bytes));
}

// ===== SGEMM v2b: BM=128 BN=64 BK=8, cp.async double-buffer =================
template<int RELU>
__global__ void __launch_bounds__(256) k_sgemm2b(
        const float* __restrict__ A, const float* __restrict__ W,
        const float* __restrict__ bias, float* __restrict__ C,
        int M, int N, int K) {
    __shared__ float As[2][128][12];
    __shared__ float Bs[2][8][64];
    const int tid = threadIdx.x;
    const int m0 = blockIdx.y * 128, n0 = blockIdx.x * 64;
    const int tx = tid & 15, ty = tid >> 4;
    const int am = tid >> 1, ah = (tid & 1) * 4;
    const int bk = tid >> 4, bn = (tid & 15) * 4;
    const float* Ap = A + (size_t)(m0 + am) * K;
    const int NIT = (K + 7) / 8;
    float acc[8][4] = {};

#define SGB_ISSUE(IT, BUF) do {                                               \
    int ka = (IT) * 8 + ah;                                                   \
    int abytes = (K - ka) * 4;                                                \
    abytes = abytes < 0 ? 0 : (abytes > 16 ? 16 : abytes);                    \
    cpa16(&As[BUF][am][ah], Ap + (abytes ? ka : 0), abytes);                  \
    if (tid < 128) {                                                          \
        int kb = (IT) * 8 + bk, n = n0 + bn;                                  \
        int bbytes = 0;                                                       \
        const float* bsrc = W;                                                \
        if (kb < K) {                                                         \
            bbytes = (N - n) * 4;                                             \
            bbytes = bbytes < 0 ? 0 : (bbytes > 16 ? 16 : bbytes);            \
            if (bbytes) bsrc = W + (size_t)kb * N + n;                        \
        }                                                                     \
        cpa16(&Bs[BUF][bk][bn], bsrc, bbytes);                                \
    }                                                                         \
    asm volatile("cp.async.commit_group;\n");                                 \
} while (0)

    SGB_ISSUE(0, 0);
    for (int it = 0; it < NIT; it++) {
        const int cur = it & 1;
        asm volatile("cp.async.wait_group 0;\n");
        __syncthreads();
        if (it + 1 < NIT) SGB_ISSUE(it + 1, cur ^ 1);
#pragma unroll
        for (int kk = 0; kk < 8; kk++) {
            float a[8], b[4];
#pragma unroll
            for (int i = 0; i < 8; i++) a[i] = As[cur][ty * 8 + i][kk];
            *(float4*)b = *(const float4*)&Bs[cur][kk][tx * 4];
#pragma unroll
            for (int i = 0; i < 8; i++)
#pragma unroll
                for (int j = 0; j < 4; j++)
                    acc[i][j] = fmaf(a[i], b[j], acc[i][j]);
        }
    }

    int n = n0 + tx * 4;
    if (n < N) {
        float4 bv = make_float4(0.f, 0.f, 0.f, 0.f);
        if (bias) bv = *(const float4*)(bias + n);
#pragma unroll
        for (int i = 0; i < 8; i++) {
            int m = m0 + ty * 8 + i;
            float4 o;
            o.x = acc[i][0] + bv.x; o.y = acc[i][1] + bv.y;
            o.z = acc[i][2] + bv.z; o.w = acc[i][3] + bv.w;
            if (RELU) {
                o.x = fmaxf(o.x, 0.f); o.y = fmaxf(o.y, 0.f);
                o.z = fmaxf(o.z, 0.f); o.w = fmaxf(o.w, 0.f);
            }
            *(float4*)(C + (size_t)m * N + n) = o;
        }
    }
}

// ===== SGEMM + highway epilogue =============================================
__global__ void __launch_bounds__(256) k_sgemm_hw(
        const float* __restrict__ A, const float* __restrict__ W,
        const float* __restrict__ bias, const float* __restrict__ hrelu,
        const float* __restrict__ x, float* __restrict__ C,
        int M, int N, int K) {
    __shared__ float As[2][128][12];
    __shared__ float Bs[2][8][64];
    const int tid = threadIdx.x;
    const int m0 = blockIdx.y * 128, n0 = blockIdx.x * 64;
    const int tx = tid & 15, ty = tid >> 4;
    const int am = tid >> 1, ah = (tid & 1) * 4;
    const int bk = tid >> 4, bn = (tid & 15) * 4;
    const float* Ap = A + (size_t)(m0 + am) * K;
    const int NIT = (K + 7) / 8;
    float acc[8][4] = {};

    SGB_ISSUE(0, 0);
    for (int it = 0; it < NIT; it++) {
        const int cur = it & 1;
        asm volatile("cp.async.wait_group 0;\n");
        __syncthreads();
        if (it + 1 < NIT) SGB_ISSUE(it + 1, cur ^ 1);
#pragma unroll
        for (int kk = 0; kk < 8; kk++) {
            float a[8], b[4];
#pragma unroll
            for (int i = 0; i < 8; i++) a[i] = As[cur][ty * 8 + i][kk];
            *(float4*)b = *(const float4*)&Bs[cur][kk][tx * 4];
#pragma unroll
            for (int i = 0; i < 8; i++)
#pragma unroll
                for (int j = 0; j < 4; j++)
                    acc[i][j] = fmaf(a[i], b[j], acc[i][j]);
        }
    }
#undef SGB_ISSUE

    int n = n0 + tx * 4;
    if (n < N) {
        float4 bv = *(const float4*)(bias + n);
#pragma unroll
        for (int i = 0; i < 8; i++) {
            int m = m0 + ty * 8 + i;
            float4 hv = *(const float4*)(hrelu + (size_t)m * N + n);
            float4 xv = *(const float4*)(x + (size_t)m * N + n);
            float4 o;
            float t0 = sigf(acc[i][0] + bv.x);
            float t1 = sigf(acc[i][1] + bv.y);
            float t2 = sigf(acc[i][2] + bv.z);
            float t3 = sigf(acc[i][3] + bv.w);
            o.x = t0 * hv.x + (1.f - t0) * xv.x;
            o.y = t1 * hv.y + (1.f - t1) * xv.y;
            o.z = t2 * hv.z + (1.f - t2) * xv.z;
            o.w = t3 * hv.w + (1.f - t3) * xv.w;
            *(float4*)(C + (size_t)m * N + n) = o;
        }
    }
}

// ===== split-K final FC with fused "final" feature construction =============
// A[m][k]: k<800 -> qfin; <1600 -> dfin; <2400 -> qfin*dfin; else qfin-dfin.
// Each 200-wide K chunk sits inside one segment (seg uniform per block).
__global__ void __launch_bounds__(256) k_fc_splitk(
        const float* __restrict__ qfin, const float* __restrict__ dfin,
        const float* __restrict__ W, float* __restrict__ part,
        int M, int N, int K) {
    __shared__ float As[8][132];
    __shared__ float Bs[8][64];
    const int tid = threadIdx.x;
    const int m0 = blockIdx.y * 128, n0 = blockIdx.x * 64;
    const int kz = blockIdx.z;
    const int klo = kz * (K / FCSPLIT), khi = klo + K / FCSPLIT;
    const int seg = klo / 800;
    const int tx = tid & 15, ty = tid >> 4;
    const int am = tid >> 1, ac = (tid & 1) * 4;
    const int bk = tid >> 4, bn = (tid & 15) * 4;
    const float* qrow = qfin + (size_t)(m0 + am) * 800;
    const float* drow = dfin + (size_t)(m0 + am) * 800;
    float acc[8][4] = {};
    for (int k0 = klo; k0 < khi; k0 += 8) {
        int jj = k0 + ac - seg * 800;
        float4 va;
        if (seg == 0) va = *(const float4*)(qrow + jj);
        else if (seg == 1) va = *(const float4*)(drow + jj);
        else {
            float4 qv = *(const float4*)(qrow + jj);
            float4 dv = *(const float4*)(drow + jj);
            if (seg == 2) {
                va.x = qv.x * dv.x; va.y = qv.y * dv.y;
                va.z = qv.z * dv.z; va.w = qv.w * dv.w;
            } else {
                va.x = qv.x - dv.x; va.y = qv.y - dv.y;
                va.z = qv.z - dv.z; va.w = qv.w - dv.w;
            }
        }
        float4 vb = make_float4(0.f, 0.f, 0.f, 0.f);
        if (tid < 128) {
            int n = n0 + bn;
            if (n < N) vb = *(const float4*)(W + (size_t)(k0 + bk) * N + n);
        }
        __syncthreads();
        As[ac][am] = va.x; As[ac + 1][am] = va.y;
        As[ac + 2][am] = va.z; As[ac + 3][am] = va.w;
        if (tid < 128) *(float4*)&Bs[bk][bn] = vb;
        __syncthreads();
#pragma unroll
        for (int kk = 0; kk < 8; kk++) {
            float a[8], b[4];
            *(float4*)(a)     = *(const float4*)&As[kk][ty * 8];
            *(float4*)(a + 4) = *(const float4*)&As[kk][ty * 8 + 4];
            *(float4*)(b)     = *(const float4*)&Bs[kk][tx * 4];
#pragma unroll
            for (int i = 0; i < 8; i++)
#pragma unroll
                for (int j = 0; j < 4; j++)
                    acc[i][j] = fmaf(a[i], b[j], acc[i][j]);
        }
    }
    int n = n0 + tx * 4;
    if (n < N) {
#pragma unroll
        for (int i = 0; i < 8; i++) {
            int m = m0 + ty * 8 + i;
            *(float4*)(part + (size_t)kz * M * N + (size_t)m * N + n) = *(float4*)&acc[i][0];
        }
    }
}

__global__ void k_fc_fin(const float* __restrict__ part, const float* __restrict__ bias,
                         float* __restrict__ out) {
    int i = blockIdx.x * blockDim.x + threadIdx.x;
    if (i >= BB * HH) return;
    float s = bias[i % HH];
#pragma unroll
    for (int z = 0; z < FCSPLIT; z++) s += part[(size_t)z * BB * HH + i];
    out[i] = fmaxf(s, 0.f);
}

// ==== batched NT v3 =========================================================
__global__ void __launch_bounds__(256) k_bgemm_nt3(
        const float* __restrict__ A, const float* __restrict__ B,
        float* __restrict__ C, int K) {
    __shared__ float As[2][8][132];
    __shared__ float Bs[2][8][132];
    const int batch = blockIdx.x;
    const float* Ab = A + (size_t)batch * LL * K;
    const float* Bb = B + (size_t)batch * LL * K;
    float* Cb = C + (size_t)batch * LL * LL;
    const int tid = threadIdx.x;
    const int tx = tid & 15, ty = tid >> 4;
    const int am = tid >> 1, ac = (tid & 1) * 4;
    const int NIT = (K + 7) / 8;
    float acc[8][8] = {};
    float4 va, vb;

#define NT_LOAD(IT) do {                                                      \
    int ka = (IT) * 8 + ac;                                                   \
    va = make_float4(0.f, 0.f, 0.f, 0.f);                                     \
    vb = make_float4(0.f, 0.f, 0.f, 0.f);                                     \
    if (ka + 3 < K) {                                                         \
        va = *(const float4*)(Ab + (size_t)am * K + ka);                      \
        vb = *(const float4*)(Bb + (size_t)am * K + ka);                      \
    } else {                                                                  \
        _Pragma("unroll")                                                     \
        for (int j = 0; j < 4; j++)                                           \
            if (ka + j < K) {                                                 \
                ((float*)&va)[j] = Ab[(size_t)am * K + ka + j];               \
                ((float*)&vb)[j] = Bb[(size_t)am * K + ka + j];               \
            }                                                                 \
    }                                                                         \
} while (0)

#define NT_STS(BUF) do {                                                      \
    _Pragma("unroll")                                                         \
    for (int j = 0; j < 4; j++) {                                             \
        As[BUF][ac + j][am] = ((float*)&va)[j];                               \
        Bs[BUF][ac + j][am] = ((float*)&vb)[j];                               \
    }                                                                         \
} while (0)

    NT_LOAD(0);
    NT_STS(0);
    __syncthreads();
    for (int it = 0; it < NIT; it++) {
        const int cur = it & 1;
        if (it + 1 < NIT) NT_LOAD(it + 1);
#pragma unroll
        for (int kk = 0; kk < 8; kk++) {
            float a[8], b[8];
            *(float4*)(a)     = *(const float4*)&As[cur][kk][ty * 8];
            *(float4*)(a + 4) = *(const float4*)&As[cur][kk][ty * 8 + 4];
            *(float4*)(b)     = *(const float4*)&Bs[cur][kk][tx * 8];
            *(float4*)(b + 4) = *(const float4*)&Bs[cur][kk][tx * 8 + 4];
#pragma unroll
            for (int i = 0; i < 8; i++)
#pragma unroll
                for (int j = 0; j < 8; j++)
                    acc[i][j] = fmaf(a[i], b[j], acc[i][j]);
        }
        if (it + 1 < NIT) {
            NT_STS(cur ^ 1);
            __syncthreads();
        }
    }
#undef NT_LOAD
#undef NT_STS
#pragma unroll
    for (int i = 0; i < 8; i++) {
        float* crow = Cb + (size_t)(ty * 8 + i) * LL + tx * 8;
        *(float4*)(crow)     = *(float4*)&acc[i][0];
        *(float4*)(crow + 4) = *(float4*)&acc[i][4];
    }
}

// ==== batched NN v3 =========================================================
__global__ void __launch_bounds__(256) k_bgemm_nn3(
        const float* __restrict__ P, const float* __restrict__ X,
        float* __restrict__ C, int N) {
    __shared__ float As[2][8][132];
    __shared__ float Bs[2][8][64];
    const int batch = blockIdx.y;
    const int n0 = blockIdx.x * 64;
    const float* Ab = P + (size_t)batch * LL * LL;
    const float* Xb = X + (size_t)batch * LL * N;
    float* Cb = C + (size_t)batch * LL * N;
    const int tid = threadIdx.x;
    const int tx = tid & 15, ty = tid >> 4;
    const int am = tid >> 1, ac = (tid & 1) * 4;
    const int bk = tid >> 4, bn = (tid & 15) * 4;
    float acc[8][4] = {};
    float4 va, vb;

#define NN_LOAD(IT) do {                                                      \
    va = *(const float4*)(Ab + (size_t)am * LL + (IT) * 8 + ac);              \
    vb = make_float4(0.f, 0.f, 0.f, 0.f);                                     \
    if (tid < 128) {                                                          \
        int n = n0 + bn;                                                      \
        if (n < N) vb = *(const float4*)(Xb + (size_t)((IT) * 8 + bk) * N + n); \
    }                                                                         \
} while (0)

#define NN_STS(BUF) do {                                                      \
    As[BUF][ac][am] = va.x; As[BUF][ac + 1][am] = va.y;                       \
    As[BUF][ac + 2][am] = va.z; As[BUF][ac + 3][am] = va.w;                   \
    if (tid < 128) *(float4*)&Bs[BUF][bk][bn] = vb;                           \
} while (0)

    NN_LOAD(0);
    NN_STS(0);
    __syncthreads();
    for (int it = 0; it < LL / 8; it++) {
        const int cur = it & 1;
        if (it + 1 < LL / 8) NN_LOAD(it + 1);
#pragma unroll
        for (int kk = 0; kk < 8; kk++) {
            float a[8], b[4];
            *(float4*)(a)     = *(const float4*)&As[cur][kk][ty * 8];
            *(float4*)(a + 4) = *(const float4*)&As[cur][kk][ty * 8 + 4];
            *(float4*)(b)     = *(const float4*)&Bs[cur][kk][tx * 4];
#pragma unroll
            for (int i = 0; i < 8; i++)
#pragma unroll
                for (int j = 0; j < 4; j++)
                    acc[i][j] = fmaf(a[i], b[j], acc[i][j]);
        }
        if (it + 1 < LL / 8) {
            NN_STS(cur ^ 1);
            __syncthreads();
        }
    }
#undef NN_LOAD
#undef NN_STS
    int n = n0 + tx * 4;
    if (n < N) {
#pragma unroll
        for (int i = 0; i < 8; i++)
            *(float4*)(Cb + (size_t)(ty * 8 + i) * N + n) = *(float4*)&acc[i][0];
    }
}

// ==== batched TN v3 =========================================================
__global__ void __launch_bounds__(256) k_bgemm_tn3(
        const float* __restrict__ P, const float* __restrict__ X,
        float* __restrict__ C, int N) {
    __shared__ float As[2][8][132];
    __shared__ float Bs[2][8][64];
    const int batch = blockIdx.y;
    const int n0 = blockIdx.x * 64;
    const float* Ab = P + (size_t)batch * LL * LL;
    const float* Xb = X + (size_t)batch * LL * N;
    float* Cb = C + (size_t)batch * LL * N;
    const int tid = threadIdx.x;
    const int tx = tid & 15, ty = tid >> 4;
    const int lk = tid >> 5, mc = (tid & 31) * 4;
    const int bk = tid >> 4, bn = (tid & 15) * 4;
    float acc[8][4] = {};
    float4 va, vb;

#define TN_LOAD(IT) do {                                                      \
    va = *(const float4*)(Ab + (size_t)((IT) * 8 + lk) * LL + mc);            \
    vb = make_float4(0.f, 0.f, 0.f, 0.f);                                     \
    if (tid < 128) {                                                          \
        int n = n0 + bn;                                                      \
        if (n < N) vb = *(const float4*)(Xb + (size_t)((IT) * 8 + bk) * N + n); \
    }                                                                         \
} while (0)

#define TN_STS(BUF) do {                                                      \
    *(float4*)&As[BUF][lk][mc] = va;                                          \
    if (tid < 128) *(float4*)&Bs[BUF][bk][bn] = vb;                           \
} while (0)

    TN_LOAD(0);
    TN_STS(0);
    __syncthreads();
    for (int it = 0; it < LL / 8; it++) {
        const int cur = it & 1;
        if (it + 1 < LL / 8) TN_LOAD(it + 1);
#pragma unroll
        for (int kk = 0; kk < 8; kk++) {
            float a[8], b[4];
            *(float4*)(a)     = *(const float4*)&As[cur][kk][ty * 8];
            *(float4*)(a + 4) = *(const float4*)&As[cur][kk][ty * 8 + 4];
            *(float4*)(b)     = *(const float4*)&Bs[cur][kk][tx * 4];
#pragma unroll
            for (int i = 0; i < 8; i++)
#pragma unroll
                for (int j = 0; j < 4; j++)
                    acc[i][j] = fmaf(a[i], b[j], acc[i][j]);
        }
        if (it + 1 < LL / 8) {
            TN_STS(cur ^ 1);
            __syncthreads();
        }
    }
#undef TN_LOAD
#undef TN_STS
    int n = n0 + tx * 4;
    if (n < N) {
#pragma unroll
        for (int i = 0; i < 8; i++)
            *(float4*)(Cb + (size_t)(ty * 8 + i) * N + n) = *(float4*)&acc[i][0];
    }
}

__global__ void k_rowred(const float* __restrict__ S, const int* __restrict__ ql,
                         const int* __restrict__ dl, float* __restrict__ rmax,
                         float* __restrict__ rsum) {
    int row = blockIdx.x * 4 + (threadIdx.x >> 5);
    int b = row / LL, q = row % LL;
    int lane = threadIdx.x & 31;
    int QL = ql[b], DL = dl[b];
    bool qv = q < QL;
    float m = NEGF, s = 0.f;
    for (int k = lane; k < LL; k += 32) {
        float v = S[(size_t)row * LL + k];
        bool valid = qv && (k < DL);
        m = fmaxf(m, valid ? v : NEGF);
        s += valid ? v : 0.f;
    }
    for (int o = 16; o; o >>= 1) {
        m = fmaxf(m, __shfl_xor_sync(0xffffffffu, m, o));
        s += __shfl_xor_sync(0xffffffffu, s, o);
    }
    if (lane == 0) { rmax[row] = m; rsum[row] = s; }
}

__global__ void k_colred(const float* __restrict__ S, const int* __restrict__ ql,
                         const int* __restrict__ dl, float* __restrict__ cmax,
                         float* __restrict__ csum) {
    int b = blockIdx.y;
    int k = blockIdx.x * 32 + threadIdx.x;
    int QL = ql[b], DL = dl[b];
    bool kv = k < DL;
    float m = NEGF, s = 0.f;
    for (int q = threadIdx.y; q < LL; q += 8) {
        float v = S[((size_t)b * LL + q) * LL + k];
        bool valid = kv && (q < QL);
        m = fmaxf(m, valid ? v : NEGF);
        s += valid ? v : 0.f;
    }
    __shared__ float sm[8][33];
    __shared__ float ss[8][33];
    sm[threadIdx.y][threadIdx.x] = m;
    ss[threadIdx.y][threadIdx.x] = s;
    __syncthreads();
    if (threadIdx.y == 0) {
        for (int r = 1; r < 8; r++) {
            m = fmaxf(m, sm[r][threadIdx.x]);
            s += ss[r][threadIdx.x];
        }
        cmax[b * LL + k] = m;
        csum[b * LL + k] = s;
    }
}

__global__ void k_softmax1d(const int* __restrict__ ql, const int* __restrict__ dl) {
    int type = blockIdx.x, b = blockIdx.y, i = threadIdx.x;
    float v;
    if (type == 0) v = g_rmax[b * LL + i];
    else if (type == 1) v = g_rsum[b * LL + i] / ((float)dl[b] + EPSI);
    else if (type == 2) v = g_cmax[b * LL + i];
    else v = g_csum[b * LL + i] / ((float)ql[b] + EPSI);
    __shared__ float red[4];
    float m = v;
    for (int o = 16; o; o >>= 1) m = fmaxf(m, __shfl_xor_sync(0xffffffffu, m, o));
    if ((i & 31) == 0) red[i >> 5] = m;
    __syncthreads();
    m = fmaxf(fmaxf(red[0], red[1]), fmaxf(red[2], red[3]));
    __syncthreads();
    float e = expf(v - m);
    float s = e;
    for (int o = 16; o; o >>= 1) s += __shfl_xor_sync(0xffffffffu, s, o);
    if ((i & 31) == 0) red[i >> 5] = s;
    __syncthreads();
    s = red[0] + red[1] + red[2] + red[3];
    g_scores[type * BB * LL + b * LL + i] = e / s;
}

__global__ void k_pool_scored(const float* __restrict__ qo, const float* __restrict__ dob) {
    int b = blockIdx.x;
    int d = threadIdx.x;
    if (d >= DD) return;
    const float* s0 = g_scores + 0 * BB * LL + b * LL;
    const float* s1 = g_scores + 1 * BB * LL + b * LL;
    const float* s2 = g_scores + 2 * BB * LL + b * LL;
    const float* s3 = g_scores + 3 * BB * LL + b * LL;
    float a0 = 0, a1 = 0, a2 = 0, a3 = 0;
    for (int t = 0; t < LL; t++) {
        float qv = qo[((size_t)b * LL + t) * DD + d];
        float dv = dob[((size_t)b * LL + t) * DD + d];
        a0 += s0[t] * qv; a1 += s1[t] * qv;
        a2 += s2[t] * dv; a3 += s3[t] * dv;
    }
    g_qmaxp[b * DD + d] = a0;
    g_qmeanp[b * DD + d] = a1;
    g_dmaxp[b * DD + d] = a2;
    g_dmeanp[b * DD + d] = a3;
}

__global__ void k_rowsoftmax(const float* __restrict__ S, float* __restrict__ P,
                             const int* __restrict__ ql, const int* __restrict__ dl,
                             int mode) {
    int q = blockIdx.x, b = blockIdx.y, k = threadIdx.x;
    bool valid;
    if (mode == 0) valid = (q < ql[b]) && (k < dl[b]);
    else if (mode == 1) valid = (k < ql[b]);
    else valid = (k < dl[b]);
    size_t idx = ((size_t)b * LL + q) * LL + k;
    float v = valid ? S[idx] : NEGF;
    __shared__ float red[4];
    float m = v;
    for (int o = 16; o; o >>= 1) m = fmaxf(m, __shfl_xor_sync(0xffffffffu, m, o));
    if ((k & 31) == 0) red[k >> 5] = m;
    __syncthreads();
    m = fmaxf(fmaxf(red[0], red[1]), fmaxf(red[2], red[3]));
    __syncthreads();
    float e = expf(v - m);
    float s = e;
    for (int o = 16; o; o >>= 1) s += __shfl_xor_sync(0xffffffffu, s, o);
    if ((k & 31) == 0) red[k >> 5] = s;
    __syncthreads();
    s = red[0] + red[1] + red[2] + red[3];
    P[idx] = e / s;
}

__global__ void k_colsoftmax(const float* __restrict__ S, float* __restrict__ P,
                             const int* __restrict__ ql, const int* __restrict__ dl) {
    int b = blockIdx.y;
    int k = blockIdx.x * 32 + threadIdx.x;
    int QL = ql[b], DL = dl[b];
    bool kv = k < DL;
    float v[16];
    float m = NEGF;
#pragma unroll
    for (int j = 0; j < 16; j++) {
        int q = threadIdx.y + 8 * j;
        bool valid = kv && (q < QL);
        v[j] = valid ? S[((size_t)b * LL + q) * LL + k] : NEGF;
        m = fmaxf(m, v[j]);
    }
    __shared__ float sm[8][33];
    sm[threadIdx.y][threadIdx.x] = m;
    __syncthreads();
    m = sm[0][threadIdx.x];
    for (int r = 1; r < 8; r++) m = fmaxf(m, sm[r][threadIdx.x]);
    __syncthreads();
    float e[16];
    float s = 0.f;
#pragma unroll
    for (int j = 0; j < 16; j++) { e[j] = expf(v[j] - m); s += e[j]; }
    sm[threadIdx.y][threadIdx.x] = s;
    __syncthreads();
    s = 0.f;
    for (int r = 0; r < 8; r++) s += sm[r][threadIdx.x];
#pragma unroll
    for (int j = 0; j < 16; j++) {
        int q = threadIdx.y + 8 * j;
        P[((size_t)b * LL + q) * LL + k] = e[j] / s;
    }
}

__global__ void k_cast(const float* __restrict__ emb, const float* __restrict__ xo,
                       const float* __restrict__ maxp, const float* __restrict__ meanp,
                       const float* __restrict__ align, const float* __restrict__ selfa,
                       const float* __restrict__ Wc, const float* __restrict__ bc,
                       const float* __restrict__ Wm, const float* __restrict__ bm,
                       const float* __restrict__ Ws, const float* __restrict__ bs,
                       int ibase, float* __restrict__ cast) {
    int bt = blockIdx.x;
    int b = bt / LL;
    int tid = threadIdx.x;
    float sc[4] = {0, 0, 0, 0}, smv[4] = {0, 0, 0, 0}, ssv[4] = {0, 0, 0, 0};
    for (int d = tid; d < DD; d += 128) {
        float e = emb[(size_t)bt * DD + d];
        float x[4];
        x[0] = maxp[b * DD + d];
        x[1] = meanp[b * DD + d];
        x[2] = align[(size_t)bt * DD + d];
        x[3] = selfa[(size_t)bt * DD + d];
#pragma unroll
        for (int i = 0; i < 4; i++) {
            const float* wc = Wc + (ibase + i) * 600;
            sc[i] += x[i] * wc[d] + e * wc[300 + d];
            smv[i] += x[i] * e * Wm[(ibase + i) * 300 + d];
            ssv[i] += (x[i] - e) * Ws[(ibase + i) * 300 + d];
        }
    }
    __shared__ float red[12][4];
    int lane = tid & 31, w = tid >> 5;
#pragma unroll
    for (int i = 0; i < 4; i++) {
        for (int o = 16; o; o >>= 1) {
            sc[i] += __shfl_xor_sync(0xffffffffu, sc[i], o);
            smv[i] += __shfl_xor_sync(0xffffffffu, smv[i], o);
            ssv[i] += __shfl_xor_sync(0xffffffffu, ssv[i], o);
        }
        if (lane == 0) {
            red[i * 3 + 0][w] = sc[i];
            red[i * 3 + 1][w] = smv[i];
            red[i * 3 + 2][w] = ssv[i];
        }
    }
    __syncthreads();
    if (tid < 12) {
        float v = red[tid][0] + red[tid][1] + red[tid][2] + red[tid][3];
        int i = tid / 3, kind = tid % 3;
        float bv = (kind == 0) ? bc[ibase + i] : (kind == 1) ? bm[ibase + i] : bs[ibase + i];
        cast[(size_t)bt * DINX + tid] = fmaxf(v + bv, 0.f);
    }
    for (int j = tid; j < DD; j += 128)
        cast[(size_t)bt * DINX + 12 + j] = xo[(size_t)bt * DD + j];
}

__global__ void k_init() {
    int i = blockIdx.x * blockDim.x + threadIdx.x;
    if (i < 16 * 32) g_barG[i] = 0u;
    if (i < 4 * BB * HH) g_h[0][i] = 0.f;
}

// ======== persistent 4-way LSTM (R11 winner: 112 blocks, float4 staging) ====
__global__ void __launch_bounds__(256, 1) k_lstm2(
        const float* __restrict__ qWh, const float* __restrict__ dWh,
        const float* __restrict__ qb, const float* __restrict__ db) {
    extern __shared__ float smx[];
    float* Ws = smx;
    float* hs = smx + 200 * 128;

    const int bx = blockIdx.x;
    const int l = bx / 28, rem = bx % 28;
    const int bt = rem / 7, ut = rem % 7;
    const int b0 = bt * 64, u0 = ut * 32;
    const int grp = l * 4 + bt;
    const int tid = threadIdx.x;
    const int tx = tid & 31, ty = tid >> 5;
    const float* Wh = ((l < 2) ? qWh : dWh) + (size_t)(l & 1) * HH * GG;
    const float* bias = ((l < 2) ? qb : db) + (size_t)(l & 1) * GG;
    float* hid = (l < 2) ? g_qhid : g_dhid;
    const int hoff = (l & 1) * HH;
    const float* Xp = g_Xpre[l];

    for (int idx = tid; idx < 200 * 128; idx += 256) {
        int k = idx >> 7, c = idx & 127;
        int uu = c >> 2, gate = c & 3;
        int u = u0 + uu;
        Ws[idx] = (u < HH) ? Wh[(size_t)k * GG + gate * HH + u] : 0.f;
    }
    const int u = u0 + tx;
    const bool uval = u < HH;
    float bv[4];
#pragma unroll
    for (int g = 0; g < 4; g++) bv[g] = uval ? bias[g * HH + u] : 0.f;
    float creg[8];
#pragma unroll
    for (int i = 0; i < 8; i++) creg[i] = 0.f;
    __syncthreads();

    for (int t = 0; t < LL; t++) {
        const int pos = (l & 1) ? (LL - 1 - t) : t;
        const float* hprev = g_h[t & 1] + l * BB * HH;

        float xv[8][4];
#pragma unroll
        for (int i = 0; i < 8; i++) {
            const float* xr = Xp + ((size_t)(b0 + ty * 8 + i) * LL + pos) * GG;
#pragma unroll
            for (int g = 0; g < 4; g++)
                xv[i][g] = uval ? xr[g * HH + u] : 0.f;
        }

        for (int idx = tid; idx < 64 * 50; idx += 256) {
            int bl = idx / 50, c4 = (idx % 50) * 4;
            float4 v = *(const float4*)(hprev + (size_t)(b0 + bl) * HH + c4);
            hs[(c4 + 0) * 68 + bl] = v.x;
            hs[(c4 + 1) * 68 + bl] = v.y;
            hs[(c4 + 2) * 68 + bl] = v.z;
            hs[(c4 + 3) * 68 + bl] = v.w;
        }
        __syncthreads();

        float acc[8][4] = {};
        const float* hp = hs + ty * 8;
        const float* wp = Ws + tx * 4;
#pragma unroll 2
        for (int k = 0; k < HH; k++) {
            float a[8], b[4];
            *(float4*)(a)     = *(const float4*)(hp + k * 68);
            *(float4*)(a + 4) = *(const float4*)(hp + k * 68 + 4);
            *(float4*)(b)     = *(const float4*)(wp + k * 128);
#pragma unroll
            for (int i = 0; i < 8; i++)
#pragma unroll
                for (int j = 0; j < 4; j++)
                    acc[i][j] = fmaf(a[i], b[j], acc[i][j]);
        }

        float* hnext = g_h[(t + 1) & 1] + l * BB * HH;
        if (uval) {
#pragma unroll
            for (int i = 0; i < 8; i++) {
                int bb = b0 + ty * 8 + i;
                float zi = acc[i][0] + xv[i][0] + bv[0];
                float zf = acc[i][1] + xv[i][1] + bv[1];
                float zg = acc[i][2] + xv[i][2] + bv[2];
                float zo = acc[i][3] + xv[i][3] + bv[3];
                float cn = sigf(zf) * creg[i] + sigf(zi) * tanhf(zg);
                float hn = sigf(zo) * tanhf(cn);
                creg[i] = cn;
                hnext[(size_t)bb * HH + u] = hn;
                hid[((size_t)bb * LL + pos) * (2 * HH) + hoff + u] = hn;
            }
        }

        __syncthreads();
        if (tid == 0) {
            __threadfence();
            atomicAdd(&g_barG[grp * 32], 1u);
            unsigned tgt = 7u * (unsigned)(t + 1);
            while (*((volatile unsigned int*)&g_barG[grp * 32]) < tgt) {}
            __threadfence();
        }
        __syncthreads();
    }
}

__global__ void k_pool(const float* __restrict__ hid, const int* __restrict__ len,
                       float* __restrict__ fin) {
    int b = blockIdx.x, tid = threadIdx.x;
    if (tid >= 400) return;
    int Lv = len[b];
    float s = 0.f, m = NEGF;
    for (int t = 0; t < LL; t++) {
        float v = (t < Lv) ? hid[((size_t)b * LL + t) * 400 + tid] : 0.f;
        s += v;
        m = fmaxf(m, v);
    }
    fin[b * 800 + tid] = s / ((float)Lv + EPSI);
    fin[b * 800 + 400 + tid] = m;
}

static float* symaddr(const void* sym) {
    void* p = nullptr;
    cudaGetSymbolAddress(&p, sym);
    return (float*)p;
}

extern "C" void kernel_launch(void* const* d_in, const int* in_sizes, int n_in,
                              void* d_out, int out_size) {
    (void)in_sizes; (void)n_in; (void)out_size;
    const float* query_emb = (const float*)d_in[0];
    const float* doc_emb   = (const float*)d_in[1];
    const int*   query_len = (const int*)d_in[2];
    const int*   doc_len   = (const int*)d_in[3];
    const float* Mw        = (const float*)d_in[4];
    const float* hwq_Wt    = (const float*)d_in[5];
    const float* hwq_bt    = (const float*)d_in[6];
    const float* hwq_Wh    = (const float*)d_in[7];
    const float* hwq_bh    = (const float*)d_in[8];
    const float* hwd_Wt    = (const float*)d_in[9];
    const float* hwd_bt    = (const float*)d_in[10];
    const float* hwd_Wh    = (const float*)d_in[11];
    const float* hwd_bh    = (const float*)d_in[12];
    const float* cWc       = (const float*)d_in[13];
    const float* cbc       = (const float*)d_in[14];
    const float* cWm       = (const float*)d_in[15];
    const float* cbm       = (const float*)d_in[16];
    const float* cWs       = (const float*)d_in[17];
    const float* cbs       = (const float*)d_in[18];
    const float* qWx       = (const float*)d_in[19];
    const float* qWh       = (const float*)d_in[20];
    const float* qb        = (const float*)d_in[21];
    const float* dWx       = (const float*)d_in[22];
    const float* dWh       = (const float*)d_in[23];
    const float* db        = (const float*)d_in[24];
    const float* fc1_W     = (const float*)d_in[25];
    const float* fc1_b     = (const float*)d_in[26];

    float* qo     = symaddr(g_qo);
    float* dob    = symaddr(g_do);
    float* tA     = symaddr(g_tA);
    float* qalign = symaddr(g_qalign);
    float* dalign = symaddr(g_dalign);
    float* qself  = symaddr(g_qself);
    float* dself  = symaddr(g_dself);
    float* S      = symaddr(g_S);
    float* P      = symaddr(g_P);
    float* qcast  = symaddr(g_qcast);
    float* dcast  = symaddr(g_dcast);
    float* Xpre   = symaddr(g_Xpre);
    float* qhid   = symaddr(g_qhid);
    float* dhid   = symaddr(g_dhid);
    float* qfin   = symaddr(g_qfin);
    float* dfin   = symaddr(g_dfin);
    float* fcpart = symaddr(g_fcpart);
    float* qmaxp  = symaddr(g_qmaxp);
    float* qmeanp = symaddr(g_qmeanp);
    float* dmaxp  = symaddr(g_dmaxp);
    float* dmeanp = symaddr(g_dmeanp);

    static int smem_set = 0;
    if (!smem_set) {
        cudaFuncSetAttribute(k_lstm2, cudaFuncAttributeMaxDynamicSharedMemorySize, LSTM_SMEM);
        smem_set = 1;
    }

    const int EW = 256;
    dim3 gD(5, 256);
    dim3 gG(13, 256);
    dim3 gB(5, BB);

    k_sgemm2b<1><<<gD, 256>>>(query_emb, hwq_Wh, hwq_bh, tA, BL, DD, DD);
    k_sgemm_hw<<<gD, 256>>>(query_emb, hwq_Wt, hwq_bt, tA, query_emb, qo, BL, DD, DD);
    k_sgemm2b<1><<<gD, 256>>>(doc_emb, hwd_Wh, hwd_bh, tA, BL, DD, DD);
    k_sgemm_hw<<<gD, 256>>>(doc_emb, hwd_Wt, hwd_bt, tA, doc_emb, dob, BL, DD, DD);

    k_sgemm2b<0><<<gD, 256>>>(qo, Mw, nullptr, tA, BL, DD, DD);
    k_bgemm_nt3<<<BB, 256>>>(tA, dob, S, DD);

    k_rowred<<<BB * LL / 4, 128>>>(S, query_len, doc_len, symaddr(g_rmax), symaddr(g_rsum));
    k_colred<<<dim3(4, BB), dim3(32, 8)>>>(S, query_len, doc_len, symaddr(g_cmax), symaddr(g_csum));
    k_softmax1d<<<dim3(4, BB), 128>>>(query_len, doc_len);
    k_pool_scored<<<BB, 320>>>(qo, dob);

    k_rowsoftmax<<<dim3(LL, BB), 128>>>(S, P, query_len, doc_len, 0);
    k_bgemm_nn3<<<gB, 256>>>(P, dob, qalign, DD);
    k_colsoftmax<<<dim3(4, BB), dim3(32, 8)>>>(S, P, query_len, doc_len);
    k_bgemm_tn3<<<gB, 256>>>(P, qo, dalign, DD);

    k_bgemm_nt3<<<BB, 256>>>(qo, qo, S, DD);
    k_rowsoftmax<<<dim3(LL, BB), 128>>>(S, P, query_len, doc_len, 1);
    k_bgemm_nn3<<<gB, 256>>>(P, qo, qself, DD);
    k_bgemm_nt3<<<BB, 256>>>(dob, dob, S, DD);
    k_rowsoftmax<<<dim3(LL, BB), 128>>>(S, P, query_len, doc_len, 2);
    k_bgemm_nn3<<<gB, 256>>>(P, dob, dself, DD);

    k_cast<<<BL, 128>>>(query_emb, qo, qmaxp, qmeanp, qalign, qself,
                        cWc, cbc, cWm, cbm, cWs, cbs, 0, qcast);
    k_cast<<<BL, 128>>>(doc_emb, dob, dmaxp, dmeanp, dalign, dself,
                        cWc, cbc, cWm, cbm, cWs, cbs, 4, dcast);

    k_sgemm2b<0><<<gG, 256>>>(qcast, qWx,             nullptr, Xpre + (size_t)0 * BL * GG, BL, GG, DINX);
    k_sgemm2b<0><<<gG, 256>>>(qcast, qWx + DINX * GG, nullptr, Xpre + (size_t)1 * BL * GG, BL, GG, DINX);
    k_sgemm2b<0><<<gG, 256>>>(dcast, dWx,             nullptr, Xpre + (size_t)2 * BL * GG, BL, GG, DINX);
    k_sgemm2b<0><<<gG, 256>>>(dcast, dWx + DINX * GG, nullptr, Xpre + (size_t)3 * BL * GG, BL, GG, DINX);

    k_init<<<(4 * BB * HH + EW - 1) / EW, EW>>>();
    k_lstm2<<<112, 256, LSTM_SMEM>>>(qWh, dWh, qb, db);

    k_pool<<<BB, 512>>>(qhid, query_len, qfin);
    k_pool<<<BB, 512>>>(dhid, doc_len, dfin);

    // split-K final FC with fused feature construction (no buildfinal pass)
    k_fc_splitk<<<dim3(4, 2, FCSPLIT), 256>>>(qfin, dfin, fc1_W, fcpart, BB, HH, 3200);
    k_fc_fin<<<(BB * HH + EW - 1) / EW, EW>>>(fcpart, fc1_b, (float*)d_out);
}

// round 14
// speedup vs baseline: 1.0570x; 1.0168x over previous
#include <cuda_runtime.h>
#include <math.h>

#define BB 256
#define LL 128
#define DD 300
#define HH 200
#define GG 800
#define DINX 312
#define BL (BB*LL)
#define NEGF (-3.402823466e38f)
#define EPSI 1e-15f
#define FCSPLIT 16
#define LSTM_SMEM 156800

static __device__ float g_qo[BL*DD];
static __device__ float g_do[BL*DD];
static __device__ float g_tA[BL*DD];
static __device__ float g_qalign[BL*DD];
static __device__ float g_dalign[BL*DD];
static __device__ float g_qself[BL*DD];
static __device__ float g_dself[BL*DD];
static __device__ float g_S[BB*LL*LL];
static __device__ float g_P[BB*LL*LL];
static __device__ float g_rmax[BB*LL];
static __device__ float g_rsum[BB*LL];
static __device__ float g_cmax[BB*LL];
static __device__ float g_csum[BB*LL];
static __device__ float g_scores[4*BB*LL];
static __device__ float g_qmaxp[BB*DD];
static __device__ float g_qmeanp[BB*DD];
static __device__ float g_dmaxp[BB*DD];
static __device__ float g_dmeanp[BB*DD];
static __device__ float g_qcast[BL*DINX];
static __device__ float g_dcast[BL*DINX];
static __device__ float g_Xpre[4][BL*GG];
static __device__ float g_h[2][4*BB*HH];
static __device__ float g_qhid[BL*2*HH];
static __device__ float g_dhid[BL*2*HH];
static __device__ float g_qfin[BB*800];
static __device__ float g_dfin[BB*800];
static __device__ float g_fcpart[FCSPLIT][BB*HH];
static __device__ unsigned int g_barG[16*32];

__device__ __forceinline__ float sigf(float x) { return 1.f / (1.f + expf(-x)); }

__device__ __forceinline__ void cpa16(void* dst, const void* src, int bytes) {
    unsigned int d = (unsigned int)__cvta_generic_to_shared(dst);
    asm volatile("cp.async.cg.shared.global [%0], [%1], 16, %2;\n"
                 :: "r"(d), "l"(src), "r"(bytes));
}

// ===== SGEMM v2b: BM=128 BN=64 BK=8, cp.async double-buffer =================
template<int RELU>
__global__ void __launch_bounds__(256) k_sgemm2b(
        const float* __restrict__ A, const float* __restrict__ W,
        const float* __restrict__ bias, float* __restrict__ C,
        int M, int N, int K) {
    __shared__ float As[2][128][12];
    __shared__ float Bs[2][8][64];
    const int tid = threadIdx.x;
    const int m0 = blockIdx.y * 128, n0 = blockIdx.x * 64;
    const int tx = tid & 15, ty = tid >> 4;
    const int am = tid >> 1, ah = (tid & 1) * 4;
    const int bk = tid >> 4, bn = (tid & 15) * 4;
    const float* Ap = A + (size_t)(m0 + am) * K;
    const int NIT = (K + 7) / 8;
    float acc[8][4] = {};

#define SGB_ISSUE(IT, BUF) do {                                               \
    int ka = (IT) * 8 + ah;                                                   \
    int abytes = (K - ka) * 4;                                                \
    abytes = abytes < 0 ? 0 : (abytes > 16 ? 16 : abytes);                    \
    cpa16(&As[BUF][am][ah], Ap + (abytes ? ka : 0), abytes);                  \
    if (tid < 128) {                                                          \
        int kb = (IT) * 8 + bk, n = n0 + bn;                                  \
        int bbytes = 0;                                                       \
        const float* bsrc = W;                                                \
        if (kb < K) {                                                         \
            bbytes = (N - n) * 4;                                             \
            bbytes = bbytes < 0 ? 0 : (bbytes > 16 ? 16 : bbytes);            \
            if (bbytes) bsrc = W + (size_t)kb * N + n;                        \
        }                                                                     \
        cpa16(&Bs[BUF][bk][bn], bsrc, bbytes);                                \
    }                                                                         \
    asm volatile("cp.async.commit_group;\n");                                 \
} while (0)

    SGB_ISSUE(0, 0);
    for (int it = 0; it < NIT; it++) {
        const int cur = it & 1;
        asm volatile("cp.async.wait_group 0;\n");
        __syncthreads();
        if (it + 1 < NIT) SGB_ISSUE(it + 1, cur ^ 1);
#pragma unroll
        for (int kk = 0; kk < 8; kk++) {
            float a[8], b[4];
#pragma unroll
            for (int i = 0; i < 8; i++) a[i] = As[cur][ty * 8 + i][kk];
            *(float4*)b = *(const float4*)&Bs[cur][kk][tx * 4];
#pragma unroll
            for (int i = 0; i < 8; i++)
#pragma unroll
                for (int j = 0; j < 4; j++)
                    acc[i][j] = fmaf(a[i], b[j], acc[i][j]);
        }
    }

    int n = n0 + tx * 4;
    if (n < N) {
        float4 bv = make_float4(0.f, 0.f, 0.f, 0.f);
        if (bias) bv = *(const float4*)(bias + n);
#pragma unroll
        for (int i = 0; i < 8; i++) {
            int m = m0 + ty * 8 + i;
            float4 o;
            o.x = acc[i][0] + bv.x; o.y = acc[i][1] + bv.y;
            o.z = acc[i][2] + bv.z; o.w = acc[i][3] + bv.w;
            if (RELU) {
                o.x = fmaxf(o.x, 0.f); o.y = fmaxf(o.y, 0.f);
                o.z = fmaxf(o.z, 0.f); o.w = fmaxf(o.w, 0.f);
            }
            *(float4*)(C + (size_t)m * N + n) = o;
        }
    }
}

// ===== SGEMM + highway epilogue =============================================
__global__ void __launch_bounds__(256) k_sgemm_hw(
        const float* __restrict__ A, const float* __restrict__ W,
        const float* __restrict__ bias, const float* __restrict__ hrelu,
        const float* __restrict__ x, float* __restrict__ C,
        int M, int N, int K) {
    __shared__ float As[2][128][12];
    __shared__ float Bs[2][8][64];
    const int tid = threadIdx.x;
    const int m0 = blockIdx.y * 128, n0 = blockIdx.x * 64;
    const int tx = tid & 15, ty = tid >> 4;
    const int am = tid >> 1, ah = (tid & 1) * 4;
    const int bk = tid >> 4, bn = (tid & 15) * 4;
    const float* Ap = A + (size_t)(m0 + am) * K;
    const int NIT = (K + 7) / 8;
    float acc[8][4] = {};

    SGB_ISSUE(0, 0);
    for (int it = 0; it < NIT; it++) {
        const int cur = it & 1;
        asm volatile("cp.async.wait_group 0;\n");
        __syncthreads();
        if (it + 1 < NIT) SGB_ISSUE(it + 1, cur ^ 1);
#pragma unroll
        for (int kk = 0; kk < 8; kk++) {
            float a[8], b[4];
#pragma unroll
            for (int i = 0; i < 8; i++) a[i] = As[cur][ty * 8 + i][kk];
            *(float4*)b = *(const float4*)&Bs[cur][kk][tx * 4];
#pragma unroll
            for (int i = 0; i < 8; i++)
#pragma unroll
                for (int j = 0; j < 4; j++)
                    acc[i][j] = fmaf(a[i], b[j], acc[i][j]);
        }
    }
#undef SGB_ISSUE

    int n = n0 + tx * 4;
    if (n < N) {
        float4 bv = *(const float4*)(bias + n);
#pragma unroll
        for (int i = 0; i < 8; i++) {
            int m = m0 + ty * 8 + i;
            float4 hv = *(const float4*)(hrelu + (size_t)m * N + n);
            float4 xv = *(const float4*)(x + (size_t)m * N + n);
            float4 o;
            float t0 = sigf(acc[i][0] + bv.x);
            float t1 = sigf(acc[i][1] + bv.y);
            float t2 = sigf(acc[i][2] + bv.z);
            float t3 = sigf(acc[i][3] + bv.w);
            o.x = t0 * hv.x + (1.f - t0) * xv.x;
            o.y = t1 * hv.y + (1.f - t1) * xv.y;
            o.z = t2 * hv.z + (1.f - t2) * xv.z;
            o.w = t3 * hv.w + (1.f - t3) * xv.w;
            *(float4*)(C + (size_t)m * N + n) = o;
        }
    }
}

// ===== split-K final FC with fused feature construction =====================
__global__ void __launch_bounds__(256) k_fc_splitk(
        const float* __restrict__ qfin, const float* __restrict__ dfin,
        const float* __restrict__ W, float* __restrict__ part,
        int M, int N, int K) {
    __shared__ float As[8][132];
    __shared__ float Bs[8][64];
    const int tid = threadIdx.x;
    const int m0 = blockIdx.y * 128, n0 = blockIdx.x * 64;
    const int kz = blockIdx.z;
    const int klo = kz * (K / FCSPLIT), khi = klo + K / FCSPLIT;
    const int seg = klo / 800;
    const int tx = tid & 15, ty = tid >> 4;
    const int am = tid >> 1, ac = (tid & 1) * 4;
    const int bk = tid >> 4, bn = (tid & 15) * 4;
    const float* qrow = qfin + (size_t)(m0 + am) * 800;
    const float* drow = dfin + (size_t)(m0 + am) * 800;
    float acc[8][4] = {};
    for (int k0 = klo; k0 < khi; k0 += 8) {
        int jj = k0 + ac - seg * 800;
        float4 va;
        if (seg == 0) va = *(const float4*)(qrow + jj);
        else if (seg == 1) va = *(const float4*)(drow + jj);
        else {
            float4 qv = *(const float4*)(qrow + jj);
            float4 dv = *(const float4*)(drow + jj);
            if (seg == 2) {
                va.x = qv.x * dv.x; va.y = qv.y * dv.y;
                va.z = qv.z * dv.z; va.w = qv.w * dv.w;
            } else {
                va.x = qv.x - dv.x; va.y = qv.y - dv.y;
                va.z = qv.z - dv.z; va.w = qv.w - dv.w;
            }
        }
        float4 vb = make_float4(0.f, 0.f, 0.f, 0.f);
        if (tid < 128) {
            int n = n0 + bn;
            if (n < N) vb = *(const float4*)(W + (size_t)(k0 + bk) * N + n);
        }
        __syncthreads();
        As[ac][am] = va.x; As[ac + 1][am] = va.y;
        As[ac + 2][am] = va.z; As[ac + 3][am] = va.w;
        if (tid < 128) *(float4*)&Bs[bk][bn] = vb;
        __syncthreads();
#pragma unroll
        for (int kk = 0; kk < 8; kk++) {
            float a[8], b[4];
            *(float4*)(a)     = *(const float4*)&As[kk][ty * 8];
            *(float4*)(a + 4) = *(const float4*)&As[kk][ty * 8 + 4];
            *(float4*)(b)     = *(const float4*)&Bs[kk][tx * 4];
#pragma unroll
            for (int i = 0; i < 8; i++)
#pragma unroll
                for (int j = 0; j < 4; j++)
                    acc[i][j] = fmaf(a[i], b[j], acc[i][j]);
        }
    }
    int n = n0 + tx * 4;
    if (n < N) {
#pragma unroll
        for (int i = 0; i < 8; i++) {
            int m = m0 + ty * 8 + i;
            *(float4*)(part + (size_t)kz * M * N + (size_t)m * N + n) = *(float4*)&acc[i][0];
        }
    }
}

__global__ void k_fc_fin(const float* __restrict__ part, const float* __restrict__ bias,
                         float* __restrict__ out) {
    int i = blockIdx.x * blockDim.x + threadIdx.x;
    if (i >= BB * HH) return;
    float s = bias[i % HH];
#pragma unroll
    for (int z = 0; z < FCSPLIT; z++) s += part[(size_t)z * BB * HH + i];
    out[i] = fmaxf(s, 0.f);
}

// ==== batched NT + fused masked row-softmax =================================
// MODE 0: cross  — write S raw, P=softmax(row), rmax/rsum (mask q<ql && k<dl)
// MODE 1: self-q — write P only (mask k<ql)
// MODE 2: self-d — write P only (mask k<dl)
template<int MODE>
__global__ void __launch_bounds__(256) k_bgemm_nt_sm(
        const float* __restrict__ A, const float* __restrict__ B,
        float* __restrict__ S, float* __restrict__ P,
        const int* __restrict__ ql, const int* __restrict__ dl,
        float* __restrict__ rmax, float* __restrict__ rsum, int K) {
    __shared__ float As[2][8][132];
    __shared__ float Bs[2][8][132];
    const int batch = blockIdx.x;
    const float* Ab = A + (size_t)batch * LL * K;
    const float* Bb = B + (size_t)batch * LL * K;
    const int tid = threadIdx.x;
    const int tx = tid & 15, ty = tid >> 4;
    const int am = tid >> 1, ac = (tid & 1) * 4;
    const int NIT = (K + 7) / 8;
    float acc[8][8] = {};
    float4 va, vb;

#define NT_LOAD(IT) do {                                                      \
    int ka = (IT) * 8 + ac;                                                   \
    va = make_float4(0.f, 0.f, 0.f, 0.f);                                     \
    vb = make_float4(0.f, 0.f, 0.f, 0.f);                                     \
    if (ka + 3 < K) {                                                         \
        va = *(const float4*)(Ab + (size_t)am * K + ka);                      \
        vb = *(const float4*)(Bb + (size_t)am * K + ka);                      \
    } else {                                                                  \
        _Pragma("unroll")                                                     \
        for (int j = 0; j < 4; j++)                                           \
            if (ka + j < K) {                                                 \
                ((float*)&va)[j] = Ab[(size_t)am * K + ka + j];               \
                ((float*)&vb)[j] = Bb[(size_t)am * K + ka + j];               \
            }                                                                 \
    }                                                                         \
} while (0)

#define NT_STS(BUF) do {                                                      \
    _Pragma("unroll")                                                         \
    for (int j = 0; j < 4; j++) {                                             \
        As[BUF][ac + j][am] = ((float*)&va)[j];                               \
        Bs[BUF][ac + j][am] = ((float*)&vb)[j];                               \
    }                                                                         \
} while (0)

    NT_LOAD(0);
    NT_STS(0);
    __syncthreads();
    for (int it = 0; it < NIT; it++) {
        const int cur = it & 1;
        if (it + 1 < NIT) NT_LOAD(it + 1);
#pragma unroll
        for (int kk = 0; kk < 8; kk++) {
            float a[8], b[8];
            *(float4*)(a)     = *(const float4*)&As[cur][kk][ty * 8];
            *(float4*)(a + 4) = *(const float4*)&As[cur][kk][ty * 8 + 4];
            *(float4*)(b)     = *(const float4*)&Bs[cur][kk][tx * 8];
            *(float4*)(b + 4) = *(const float4*)&Bs[cur][kk][tx * 8 + 4];
#pragma unroll
            for (int i = 0; i < 8; i++)
#pragma unroll
                for (int j = 0; j < 8; j++)
                    acc[i][j] = fmaf(a[i], b[j], acc[i][j]);
        }
        if (it + 1 < NIT) {
            NT_STS(cur ^ 1);
            __syncthreads();
        }
    }
#undef NT_LOAD
#undef NT_STS

    const int QL = ql[batch], DL = dl[batch];
    const int KM = (MODE == 1) ? QL : DL;   // column mask limit (modes 1/2, and k-part of mode 0)
    float* Pb = P + (size_t)batch * LL * LL;
#pragma unroll
    for (int i = 0; i < 8; i++) {
        const int r = ty * 8 + i;
        const bool rv = (MODE != 0) || (r < QL);
        float v[8];
        float m = NEGF, s = 0.f;
#pragma unroll
        for (int j = 0; j < 8; j++) {
            int k = tx * 8 + j;
            bool valid = rv && (k < KM);
            v[j] = valid ? acc[i][j] : NEGF;
            m = fmaxf(m, v[j]);
            if (MODE == 0) s += valid ? acc[i][j] : 0.f;
        }
#pragma unroll
        for (int o = 8; o; o >>= 1)
            m = fmaxf(m, __shfl_xor_sync(0xffffffffu, m, o));
        float e[8];
        float es = 0.f;
#pragma unroll
        for (int j = 0; j < 8; j++) { e[j] = expf(v[j] - m); es += e[j]; }
#pragma unroll
        for (int o = 8; o; o >>= 1)
            es += __shfl_xor_sync(0xffffffffu, es, o);
        float inv = 1.f / es;
        float4 p0, p1;
        p0.x = e[0] * inv; p0.y = e[1] * inv; p0.z = e[2] * inv; p0.w = e[3] * inv;
        p1.x = e[4] * inv; p1.y = e[5] * inv; p1.z = e[6] * inv; p1.w = e[7] * inv;
        *(float4*)(Pb + (size_t)r * LL + tx * 8)     = p0;
        *(float4*)(Pb + (size_t)r * LL + tx * 8 + 4) = p1;
        if (MODE == 0) {
            float* srow = S + ((size_t)batch * LL + r) * LL + tx * 8;
            *(float4*)(srow)     = *(float4*)&acc[i][0];
            *(float4*)(srow + 4) = *(float4*)&acc[i][4];
#pragma unroll
            for (int o = 8; o; o >>= 1)
                s += __shfl_xor_sync(0xffffffffu, s, o);
            if (tx == 0) {
                rmax[batch * LL + r] = m;
                rsum[batch * LL + r] = s;
            }
        }
    }
}

// ==== batched NN v3 =========================================================
__global__ void __launch_bounds__(256) k_bgemm_nn3(
        const float* __restrict__ P, const float* __restrict__ X,
        float* __restrict__ C, int N) {
    __shared__ float As[2][8][132];
    __shared__ float Bs[2][8][64];
    const int batch = blockIdx.y;
    const int n0 = blockIdx.x * 64;
    const float* Ab = P + (size_t)batch * LL * LL;
    const float* Xb = X + (size_t)batch * LL * N;
    float* Cb = C + (size_t)batch * LL * N;
    const int tid = threadIdx.x;
    const int tx = tid & 15, ty = tid >> 4;
    const int am = tid >> 1, ac = (tid & 1) * 4;
    const int bk = tid >> 4, bn = (tid & 15) * 4;
    float acc[8][4] = {};
    float4 va, vb;

#define NN_LOAD(IT) do {                                                      \
    va = *(const float4*)(Ab + (size_t)am * LL + (IT) * 8 + ac);              \
    vb = make_float4(0.f, 0.f, 0.f, 0.f);                                     \
    if (tid < 128) {                                                          \
        int n = n0 + bn;                                                      \
        if (n < N) vb = *(const float4*)(Xb + (size_t)((IT) * 8 + bk) * N + n); \
    }                                                                         \
} while (0)

#define NN_STS(BUF) do {                                                      \
    As[BUF][ac][am] = va.x; As[BUF][ac + 1][am] = va.y;                       \
    As[BUF][ac + 2][am] = va.z; As[BUF][ac + 3][am] = va.w;                   \
    if (tid < 128) *(float4*)&Bs[BUF][bk][bn] = vb;                           \
} while (0)

    NN_LOAD(0);
    NN_STS(0);
    __syncthreads();
    for (int it = 0; it < LL / 8; it++) {
        const int cur = it & 1;
        if (it + 1 < LL / 8) NN_LOAD(it + 1);
#pragma unroll
        for (int kk = 0; kk < 8; kk++) {
            float a[8], b[4];
            *(float4*)(a)     = *(const float4*)&As[cur][kk][ty * 8];
            *(float4*)(a + 4) = *(const float4*)&As[cur][kk][ty * 8 + 4];
            *(float4*)(b)     = *(const float4*)&Bs[cur][kk][tx * 4];
#pragma unroll
            for (int i = 0; i < 8; i++)
#pragma unroll
                for (int j = 0; j < 4; j++)
                    acc[i][j] = fmaf(a[i], b[j], acc[i][j]);
        }
        if (it + 1 < LL / 8) {
            NN_STS(cur ^ 1);
            __syncthreads();
        }
    }
#undef NN_LOAD
#undef NN_STS
    int n = n0 + tx * 4;
    if (n < N) {
#pragma unroll
        for (int i = 0; i < 8; i++)
            *(float4*)(Cb + (size_t)(ty * 8 + i) * N + n) = *(float4*)&acc[i][0];
    }
}

// ==== batched TN v3 =========================================================
__global__ void __launch_bounds__(256) k_bgemm_tn3(
        const float* __restrict__ P, const float* __restrict__ X,
        float* __restrict__ C, int N) {
    __shared__ float As[2][8][132];
    __shared__ float Bs[2][8][64];
    const int batch = blockIdx.y;
    const int n0 = blockIdx.x * 64;
    const float* Ab = P + (size_t)batch * LL * LL;
    const float* Xb = X + (size_t)batch * LL * N;
    float* Cb = C + (size_t)batch * LL * N;
    const int tid = threadIdx.x;
    const int tx = tid & 15, ty = tid >> 4;
    const int lk = tid >> 5, mc = (tid & 31) * 4;
    const int bk = tid >> 4, bn = (tid & 15) * 4;
    float acc[8][4] = {};
    float4 va, vb;

#define TN_LOAD(IT) do {                                                      \
    va = *(const float4*)(Ab + (size_t)((IT) * 8 + lk) * LL + mc);            \
    vb = make_float4(0.f, 0.f, 0.f, 0.f);                                     \
    if (tid < 128) {                                                          \
        int n = n0 + bn;                                                      \
        if (n < N) vb = *(const float4*)(Xb + (size_t)((IT) * 8 + bk) * N + n); \
    }                                                                         \
} while (0)

#define TN_STS(BUF) do {                                                      \
    *(float4*)&As[BUF][lk][mc] = va;                                          \
    if (tid < 128) *(float4*)&Bs[BUF][bk][bn] = vb;                           \
} while (0)

    TN_LOAD(0);
    TN_STS(0);
    __syncthreads();
    for (int it = 0; it < LL / 8; it++) {
        const int cur = it & 1;
        if (it + 1 < LL / 8) TN_LOAD(it + 1);
#pragma unroll
        for (int kk = 0; kk < 8; kk++) {
            float a[8], b[4];
            *(float4*)(a)     = *(const float4*)&As[cur][kk][ty * 8];
            *(float4*)(a + 4) = *(const float4*)&As[cur][kk][ty * 8 + 4];
            *(float4*)(b)     = *(const float4*)&Bs[cur][kk][tx * 4];
#pragma unroll
            for (int i = 0; i < 8; i++)
#pragma unroll
                for (int j = 0; j < 4; j++)
                    acc[i][j] = fmaf(a[i], b[j], acc[i][j]);
        }
        if (it + 1 < LL / 8) {
            TN_STS(cur ^ 1);
            __syncthreads();
        }
    }
#undef TN_LOAD
#undef TN_STS
    int n = n0 + tx * 4;
    if (n < N) {
#pragma unroll
        for (int i = 0; i < 8; i++)
            *(float4*)(Cb + (size_t)(ty * 8 + i) * N + n) = *(float4*)&acc[i][0];
    }
}

__global__ void k_colred(const float* __restrict__ S, const int* __restrict__ ql,
                         const int* __restrict__ dl, float* __restrict__ cmax,
                         float* __restrict__ csum) {
    int b = blockIdx.y;
    int k = blockIdx.x * 32 + threadIdx.x;
    int QL = ql[b], DL = dl[b];
    bool kv = k < DL;
    float m = NEGF, s = 0.f;
    for (int q = threadIdx.y; q < LL; q += 8) {
        float v = S[((size_t)b * LL + q) * LL + k];
        bool valid = kv && (q < QL);
        m = fmaxf(m, valid ? v : NEGF);
        s += valid ? v : 0.f;
    }
    __shared__ float sm[8][33];
    __shared__ float ss[8][33];
    sm[threadIdx.y][threadIdx.x] = m;
    ss[threadIdx.y][threadIdx.x] = s;
    __syncthreads();
    if (threadIdx.y == 0) {
        for (int r = 1; r < 8; r++) {
            m = fmaxf(m, sm[r][threadIdx.x]);
            s += ss[r][threadIdx.x];
        }
        cmax[b * LL + k] = m;
        csum[b * LL + k] = s;
    }
}

__global__ void k_softmax1d(const int* __restrict__ ql, const int* __restrict__ dl) {
    int type = blockIdx.x, b = blockIdx.y, i = threadIdx.x;
    float v;
    if (type == 0) v = g_rmax[b * LL + i];
    else if (type == 1) v = g_rsum[b * LL + i] / ((float)dl[b] + EPSI);
    else if (type == 2) v = g_cmax[b * LL + i];
    else v = g_csum[b * LL + i] / ((float)ql[b] + EPSI);
    __shared__ float red[4];
    float m = v;
    for (int o = 16; o; o >>= 1) m = fmaxf(m, __shfl_xor_sync(0xffffffffu, m, o));
    if ((i & 31) == 0) red[i >> 5] = m;
    __syncthreads();
    m = fmaxf(fmaxf(red[0], red[1]), fmaxf(red[2], red[3]));
    __syncthreads();
    float e = expf(v - m);
    float s = e;
    for (int o = 16; o; o >>= 1) s += __shfl_xor_sync(0xffffffffu, s, o);
    if ((i & 31) == 0) red[i >> 5] = s;
    __syncthreads();
    s = red[0] + red[1] + red[2] + red[3];
    g_scores[type * BB * LL + b * LL + i] = e / s;
}

__global__ void k_pool_scored(const float* __restrict__ qo, const float* __restrict__ dob) {
    int b = blockIdx.x;
    int d = threadIdx.x;
    if (d >= DD) return;
    const float* s0 = g_scores + 0 * BB * LL + b * LL;
    const float* s1 = g_scores + 1 * BB * LL + b * LL;
    const float* s2 = g_scores + 2 * BB * LL + b * LL;
    const float* s3 = g_scores + 3 * BB * LL + b * LL;
    float a0 = 0, a1 = 0, a2 = 0, a3 = 0;
    for (int t = 0; t < LL; t++) {
        float qv = qo[((size_t)b * LL + t) * DD + d];
        float dv = dob[((size_t)b * LL + t) * DD + d];
        a0 += s0[t] * qv; a1 += s1[t] * qv;
        a2 += s2[t] * dv; a3 += s3[t] * dv;
    }
    g_qmaxp[b * DD + d] = a0;
    g_qmeanp[b * DD + d] = a1;
    g_dmaxp[b * DD + d] = a2;
    g_dmeanp[b * DD + d] = a3;
}

__global__ void k_colsoftmax(const float* __restrict__ S, float* __restrict__ P,
                             const int* __restrict__ ql, const int* __restrict__ dl) {
    int b = blockIdx.y;
    int k = blockIdx.x * 32 + threadIdx.x;
    int QL = ql[b], DL = dl[b];
    bool kv = k < DL;
    float v[16];
    float m = NEGF;
#pragma unroll
    for (int j = 0; j < 16; j++) {
        int q = threadIdx.y + 8 * j;
        bool valid = kv && (q < QL);
        v[j] = valid ? S[((size_t)b * LL + q) * LL + k] : NEGF;
        m = fmaxf(m, v[j]);
    }
    __shared__ float sm[8][33];
    sm[threadIdx.y][threadIdx.x] = m;
    __syncthreads();
    m = sm[0][threadIdx.x];
    for (int r = 1; r < 8; r++) m = fmaxf(m, sm[r][threadIdx.x]);
    __syncthreads();
    float e[16];
    float s = 0.f;
#pragma unroll
    for (int j = 0; j < 16; j++) { e[j] = expf(v[j] - m); s += e[j]; }
    sm[threadIdx.y][threadIdx.x] = s;
    __syncthreads();
    s = 0.f;
    for (int r = 0; r < 8; r++) s += sm[r][threadIdx.x];
#pragma unroll
    for (int j = 0; j < 16; j++) {
        int q = threadIdx.y + 8 * j;
        P[((size_t)b * LL + q) * LL + k] = e[j] / s;
    }
}

__global__ void k_cast(const float* __restrict__ emb, const float* __restrict__ xo,
                       const float* __restrict__ maxp, const float* __restrict__ meanp,
                       const float* __restrict__ align, const float* __restrict__ selfa,
                       const float* __restrict__ Wc, const float* __restrict__ bc,
                       const float* __restrict__ Wm, const float* __restrict__ bm,
                       const float* __restrict__ Ws, const float* __restrict__ bs,
                       int ibase, float* __restrict__ cast) {
    int bt = blockIdx.x;
    int b = bt / LL;
    int tid = threadIdx.x;
    float sc[4] = {0, 0, 0, 0}, smv[4] = {0, 0, 0, 0}, ssv[4] = {0, 0, 0, 0};
    for (int d = tid; d < DD; d += 128) {
        float e = emb[(size_t)bt * DD + d];
        float x[4];
        x[0] = maxp[b * DD + d];
        x[1] = meanp[b * DD + d];
        x[2] = align[(size_t)bt * DD + d];
        x[3] = selfa[(size_t)bt * DD + d];
#pragma unroll
        for (int i = 0; i < 4; i++) {
            const float* wc = Wc + (ibase + i) * 600;
            sc[i] += x[i] * wc[d] + e * wc[300 + d];
            smv[i] += x[i] * e * Wm[(ibase + i) * 300 + d];
            ssv[i] += (x[i] - e) * Ws[(ibase + i) * 300 + d];
        }
    }
    __shared__ float red[12][4];
    int lane = tid & 31, w = tid >> 5;
#pragma unroll
    for (int i = 0; i < 4; i++) {
        for (int o = 16; o; o >>= 1) {
            sc[i] += __shfl_xor_sync(0xffffffffu, sc[i], o);
            smv[i] += __shfl_xor_sync(0xffffffffu, smv[i], o);
            ssv[i] += __shfl_xor_sync(0xffffffffu, ssv[i], o);
        }
        if (lane == 0) {
            red[i * 3 + 0][w] = sc[i];
            red[i * 3 + 1][w] = smv[i];
            red[i * 3 + 2][w] = ssv[i];
        }
    }
    __syncthreads();
    if (tid < 12) {
        float v = red[tid][0] + red[tid][1] + red[tid][2] + red[tid][3];
        int i = tid / 3, kind = tid % 3;
        float bv = (kind == 0) ? bc[ibase + i] : (kind == 1) ? bm[ibase + i] : bs[ibase + i];
        cast[(size_t)bt * DINX + tid] = fmaxf(v + bv, 0.f);
    }
    for (int j = tid; j < DD; j += 128)
        cast[(size_t)bt * DINX + 12 + j] = xo[(size_t)bt * DD + j];
}

__global__ void k_init() {
    int i = blockIdx.x * blockDim.x + threadIdx.x;
    if (i < 16 * 32) g_barG[i] = 0u;
    if (i < 4 * BB * HH) g_h[0][i] = 0.f;
}

// ======== persistent 4-way LSTM (112 blocks, float4 staging) ================
__global__ void __launch_bounds__(256, 1) k_lstm2(
        const float* __restrict__ qWh, const float* __restrict__ dWh,
        const float* __restrict__ qb, const float* __restrict__ db) {
    extern __shared__ float smx[];
    float* Ws = smx;
    float* hs = smx + 200 * 128;

    const int bx = blockIdx.x;
    const int l = bx / 28, rem = bx % 28;
    const int bt = rem / 7, ut = rem % 7;
    const int b0 = bt * 64, u0 = ut * 32;
    const int grp = l * 4 + bt;
    const int tid = threadIdx.x;
    const int tx = tid & 31, ty = tid >> 5;
    const float* Wh = ((l < 2) ? qWh : dWh) + (size_t)(l & 1) * HH * GG;
    const float* bias = ((l < 2) ? qb : db) + (size_t)(l & 1) * GG;
    float* hid = (l < 2) ? g_qhid : g_dhid;
    const int hoff = (l & 1) * HH;
    const float* Xp = g_Xpre[l];

    for (int idx = tid; idx < 200 * 128; idx += 256) {
        int k = idx >> 7, c = idx & 127;
        int uu = c >> 2, gate = c & 3;
        int u = u0 + uu;
        Ws[idx] = (u < HH) ? Wh[(size_t)k * GG + gate * HH + u] : 0.f;
    }
    const int u = u0 + tx;
    const bool uval = u < HH;
    float bv[4];
#pragma unroll
    for (int g = 0; g < 4; g++) bv[g] = uval ? bias[g * HH + u] : 0.f;
    float creg[8];
#pragma unroll
    for (int i = 0; i < 8; i++) creg[i] = 0.f;
    __syncthreads();

    for (int t = 0; t < LL; t++) {
        const int pos = (l & 1) ? (LL - 1 - t) : t;
        const float* hprev = g_h[t & 1] + l * BB * HH;

        float xv[8][4];
#pragma unroll
        for (int i = 0; i < 8; i++) {
            const float* xr = Xp + ((size_t)(b0 + ty * 8 + i) * LL + pos) * GG;
#pragma unroll
            for (int g = 0; g < 4; g++)
                xv[i][g] = uval ? xr[g * HH + u] : 0.f;
        }

        for (int idx = tid; idx < 64 * 50; idx += 256) {
            int bl = idx / 50, c4 = (idx % 50) * 4;
            float4 v = *(const float4*)(hprev + (size_t)(b0 + bl) * HH + c4);
            hs[(c4 + 0) * 68 + bl] = v.x;
            hs[(c4 + 1) * 68 + bl] = v.y;
            hs[(c4 + 2) * 68 + bl] = v.z;
            hs[(c4 + 3) * 68 + bl] = v.w;
        }
        __syncthreads();

        float acc[8][4] = {};
        const float* hp = hs + ty * 8;
        const float* wp = Ws + tx * 4;
#pragma unroll 2
        for (int k = 0; k < HH; k++) {
            float a[8], b[4];
            *(float4*)(a)     = *(const float4*)(hp + k * 68);
            *(float4*)(a + 4) = *(const float4*)(hp + k * 68 + 4);
            *(float4*)(b)     = *(const float4*)(wp + k * 128);
#pragma unroll
            for (int i = 0; i < 8; i++)
#pragma unroll
                for (int j = 0; j < 4; j++)
                    acc[i][j] = fmaf(a[i], b[j], acc[i][j]);
        }

        float* hnext = g_h[(t + 1) & 1] + l * BB * HH;
        if (uval) {
#pragma unroll
            for (int i = 0; i < 8; i++) {
                int bb = b0 + ty * 8 + i;
                float zi = acc[i][0] + xv[i][0] + bv[0];
                float zf = acc[i][1] + xv[i][1] + bv[1];
                float zg = acc[i][2] + xv[i][2] + bv[2];
                float zo = acc[i][3] + xv[i][3] + bv[3];
                float cn = sigf(zf) * creg[i] + sigf(zi) * tanhf(zg);
                float hn = sigf(zo) * tanhf(cn);
                creg[i] = cn;
                hnext[(size_t)bb * HH + u] = hn;
                hid[((size_t)bb * LL + pos) * (2 * HH) + hoff + u] = hn;
            }
        }

        __syncthreads();
        if (tid == 0) {
            __threadfence();
            atomicAdd(&g_barG[grp * 32], 1u);
            unsigned tgt = 7u * (unsigned)(t + 1);
            while (*((volatile unsigned int*)&g_barG[grp * 32]) < tgt) {}
            __threadfence();
        }
        __syncthreads();
    }
}

__global__ void k_pool(const float* __restrict__ hid, const int* __restrict__ len,
                       float* __restrict__ fin) {
    int b = blockIdx.x, tid = threadIdx.x;
    if (tid >= 400) return;
    int Lv = len[b];
    float s = 0.f, m = NEGF;
    for (int t = 0; t < LL; t++) {
        float v = (t < Lv) ? hid[((size_t)b * LL + t) * 400 + tid] : 0.f;
        s += v;
        m = fmaxf(m, v);
    }
    fin[b * 800 + tid] = s / ((float)Lv + EPSI);
    fin[b * 800 + 400 + tid] = m;
}

static float* symaddr(const void* sym) {
    void* p = nullptr;
    cudaGetSymbolAddress(&p, sym);
    return (float*)p;
}

extern "C" void kernel_launch(void* const* d_in, const int* in_sizes, int n_in,
                              void* d_out, int out_size) {
    (void)in_sizes; (void)n_in; (void)out_size;
    const float* query_emb = (const float*)d_in[0];
    const float* doc_emb   = (const float*)d_in[1];
    const int*   query_len = (const int*)d_in[2];
    const int*   doc_len   = (const int*)d_in[3];
    const float* Mw        = (const float*)d_in[4];
    const float* hwq_Wt    = (const float*)d_in[5];
    const float* hwq_bt    = (const float*)d_in[6];
    const float* hwq_Wh    = (const float*)d_in[7];
    const float* hwq_bh    = (const float*)d_in[8];
    const float* hwd_Wt    = (const float*)d_in[9];
    const float* hwd_bt    = (const float*)d_in[10];
    const float* hwd_Wh    = (const float*)d_in[11];
    const float* hwd_bh    = (const float*)d_in[12];
    const float* cWc       = (const float*)d_in[13];
    const float* cbc       = (const float*)d_in[14];
    const float* cWm       = (const float*)d_in[15];
    const float* cbm       = (const float*)d_in[16];
    const float* cWs       = (const float*)d_in[17];
    const float* cbs       = (const float*)d_in[18];
    const float* qWx       = (const float*)d_in[19];
    const float* qWh       = (const float*)d_in[20];
    const float* qb        = (const float*)d_in[21];
    const float* dWx       = (const float*)d_in[22];
    const float* dWh       = (const float*)d_in[23];
    const float* db        = (const float*)d_in[24];
    const float* fc1_W     = (const float*)d_in[25];
    const float* fc1_b     = (const float*)d_in[26];

    float* qo     = symaddr(g_qo);
    float* dob    = symaddr(g_do);
    float* tA     = symaddr(g_tA);
    float* qalign = symaddr(g_qalign);
    float* dalign = symaddr(g_dalign);
    float* qself  = symaddr(g_qself);
    float* dself  = symaddr(g_dself);
    float* S      = symaddr(g_S);
    float* P      = symaddr(g_P);
    float* qcast  = symaddr(g_qcast);
    float* dcast  = symaddr(g_dcast);
    float* Xpre   = symaddr(g_Xpre);
    float* qhid   = symaddr(g_qhid);
    float* dhid   = symaddr(g_dhid);
    float* qfin   = symaddr(g_qfin);
    float* dfin   = symaddr(g_dfin);
    float* fcpart = symaddr(g_fcpart);
    float* qmaxp  = symaddr(g_qmaxp);
    float* qmeanp = symaddr(g_qmeanp);
    float* dmaxp  = symaddr(g_dmaxp);
    float* dmeanp = symaddr(g_dmeanp);
    float* rmax   = symaddr(g_rmax);
    float* rsum   = symaddr(g_rsum);

    static int smem_set = 0;
    if (!smem_set) {
        cudaFuncSetAttribute(k_lstm2, cudaFuncAttributeMaxDynamicSharedMemorySize, LSTM_SMEM);
        smem_set = 1;
    }

    const int EW = 256;
    dim3 gD(5, 256);
    dim3 gG(13, 256);
    dim3 gB(5, BB);

    k_sgemm2b<1><<<gD, 256>>>(query_emb, hwq_Wh, hwq_bh, tA, BL, DD, DD);
    k_sgemm_hw<<<gD, 256>>>(query_emb, hwq_Wt, hwq_bt, tA, query_emb, qo, BL, DD, DD);
    k_sgemm2b<1><<<gD, 256>>>(doc_emb, hwd_Wh, hwd_bh, tA, BL, DD, DD);
    k_sgemm_hw<<<gD, 256>>>(doc_emb, hwd_Wt, hwd_bt, tA, doc_emb, dob, BL, DD, DD);

    // cross: S + P(row-softmax) + rmax/rsum fused into the NT epilogue
    k_sgemm2b<0><<<gD, 256>>>(qo, Mw, nullptr, tA, BL, DD, DD);
    k_bgemm_nt_sm<0><<<BB, 256>>>(tA, dob, S, P, query_len, doc_len, rmax, rsum, DD);

    k_colred<<<dim3(4, BB), dim3(32, 8)>>>(S, query_len, doc_len, symaddr(g_cmax), symaddr(g_csum));
    k_softmax1d<<<dim3(4, BB), 128>>>(query_len, doc_len);
    k_pool_scored<<<BB, 320>>>(qo, dob);

    k_bgemm_nn3<<<gB, 256>>>(P, dob, qalign, DD);
    k_colsoftmax<<<dim3(4, BB), dim3(32, 8)>>>(S, P, query_len, doc_len);
    k_bgemm_tn3<<<gB, 256>>>(P, qo, dalign, DD);

    // self attention: P fused into NT epilogue, S never materialized
    k_bgemm_nt_sm<1><<<BB, 256>>>(qo, qo, nullptr, P, query_len, doc_len, nullptr, nullptr, DD);
    k_bgemm_nn3<<<gB, 256>>>(P, qo, qself, DD);
    k_bgemm_nt_sm<2><<<BB, 256>>>(dob, dob, nullptr, P, query_len, doc_len, nullptr, nullptr, DD);
    k_bgemm_nn3<<<gB, 256>>>(P, dob, dself, DD);

    k_cast<<<BL, 128>>>(query_emb, qo, qmaxp, qmeanp, qalign, qself,
                        cWc, cbc, cWm, cbm, cWs, cbs, 0, qcast);
    k_cast<<<BL, 128>>>(doc_emb, dob, dmaxp, dmeanp, dalign, dself,
                        cWc, cbc, cWm, cbm, cWs, cbs, 4, dcast);

    k_sgemm2b<0><<<gG, 256>>>(qcast, qWx,             nullptr, Xpre + (size_t)0 * BL * GG, BL, GG, DINX);
    k_sgemm2b<0><<<gG, 256>>>(qcast, qWx + DINX * GG, nullptr, Xpre + (size_t)1 * BL * GG, BL, GG, DINX);
    k_sgemm2b<0><<<gG, 256>>>(dcast, dWx,             nullptr, Xpre + (size_t)2 * BL * GG, BL, GG, DINX);
    k_sgemm2b<0><<<gG, 256>>>(dcast, dWx + DINX * GG, nullptr, Xpre + (size_t)3 * BL * GG, BL, GG, DINX);

    k_init<<<(4 * BB * HH + EW - 1) / EW, EW>>>();
    k_lstm2<<<112, 256, LSTM_SMEM>>>(qWh, dWh, qb, db);

    k_pool<<<BB, 512>>>(qhid, query_len, qfin);
    k_pool<<<BB, 512>>>(dhid, doc_len, dfin);

    k_fc_splitk<<<dim3(4, 2, FCSPLIT), 256>>>(qfin, dfin, fc1_W, fcpart, BB, HH, 3200);
    k_fc_fin<<<(BB * HH + EW - 1) / EW, EW>>>(fcpart, fc1_b, (float*)d_out);
}